// round 6
// baseline (speedup 1.0000x reference)
#include <cuda_runtime.h>
#include <cuda_bf16.h>
#include <math.h>
#include <stdint.h>

// ----------------------------------------------------------------------------
// Problem constants
// ----------------------------------------------------------------------------
#define B      2
#define N_SEQ  2048
#define DIM    2048
#define HEADS  16
#define DHEAD  128
#define INNER  (HEADS * DHEAD)       // 2048
#define ROWS   (B * N_SEQ)           // 4096

// ----------------------------------------------------------------------------
// Scratch (device globals; no allocations allowed)
// ----------------------------------------------------------------------------
__device__ float g_xn[ROWS * DIM];
__device__ float g_q [ROWS * INNER];
__device__ float g_kv[ROWS * 2 * INNER];
__device__ float g_o [ROWS * INNER];

// ----------------------------------------------------------------------------
// helpers
// ----------------------------------------------------------------------------
__device__ __forceinline__ uint32_t f2tf32(float f) {
    uint32_t u;
    asm("cvt.rna.tf32.f32 %0, %1;" : "=r"(u) : "f"(f));
    return u;
}

__device__ __forceinline__ float fex2(float x) {   // hardware MUFU exp2
    float y;
    asm("ex2.approx.ftz.f32 %0, %1;" : "=f"(y) : "f"(x));
    return y;
}

__device__ __forceinline__ void mma_tf32(float* c, const uint32_t* a, const uint32_t* b) {
    asm volatile(
        "mma.sync.aligned.m16n8k8.row.col.f32.tf32.tf32.f32 "
        "{%0,%1,%2,%3},{%4,%5,%6,%7},{%8,%9},{%0,%1,%2,%3};"
        : "+f"(c[0]), "+f"(c[1]), "+f"(c[2]), "+f"(c[3])
        : "r"(a[0]), "r"(a[1]), "r"(a[2]), "r"(a[3]), "r"(b[0]), "r"(b[1]));
}

// ----------------------------------------------------------------------------
// RMSNorm
// ----------------------------------------------------------------------------
__global__ __launch_bounds__(256) void rmsnorm_kernel(
    const float* __restrict__ x, const float* __restrict__ g,
    float* __restrict__ xn)
{
    const int row = blockIdx.x;
    const float* xr = x  + (size_t)row * DIM;
    float*       xo = xn + (size_t)row * DIM;

    float ss = 0.f;
    for (int i = threadIdx.x; i < DIM; i += 256) {
        float v = xr[i];
        ss += v * v;
    }
    __shared__ float red[8];
    #pragma unroll
    for (int o = 16; o > 0; o >>= 1) ss += __shfl_xor_sync(0xffffffffu, ss, o);
    if ((threadIdx.x & 31) == 0) red[threadIdx.x >> 5] = ss;
    __syncthreads();
    if (threadIdx.x < 8) {
        float v = red[threadIdx.x];
        #pragma unroll
        for (int o = 4; o > 0; o >>= 1) v += __shfl_xor_sync(0x000000ffu, v, o);
        if (threadIdx.x == 0) red[0] = v;
    }
    __syncthreads();
    const float rms = sqrtf(red[0] * (1.f / (float)DIM));
    const float inv = 1.f / fmaxf(rms, 1e-8f);
    for (int i = threadIdx.x; i < DIM; i += 256)
        xo[i] = xr[i] * inv * g[i];
}

// ----------------------------------------------------------------------------
// TF32 tensor-core GEMM, double-buffered smem, tf32 conversion at smem store.
// (unchanged from round 5)
// ----------------------------------------------------------------------------
#define T_BM 128
#define T_BN 128
#define T_BK 16
#define AS_STRIDE 20
#define BS_STRIDE 136

__global__ __launch_bounds__(256, 2) void tf32_gemm_kernel(
    int M, int N, int K,
    const float* __restrict__ A, const float* __restrict__ Bm,
    float* __restrict__ C)
{
    __shared__ float As[2][T_BM][AS_STRIDE];
    __shared__ float Bs[2][T_BK][BS_STRIDE];

    const int tid  = threadIdx.x;
    const int lane = tid & 31;
    const int warp = tid >> 5;
    const int wm   = warp >> 1;
    const int wn   = warp & 1;
    const int mbase = wm * 32;
    const int nbase = wn * 64;

    const int aRow = tid >> 2;
    const int aCol = (tid & 3) * 4;
    const int bRow = tid >> 5;
    const int bCol = (tid & 31) * 4;

    const float* Ap = A  + (size_t)blockIdx.y * T_BM * K;
    const float* Bp = Bm + (size_t)blockIdx.x * T_BN;

    float4 aReg[2], bReg[2];
    aReg[0] = *(const float4*)(Ap + (size_t)aRow        * K + aCol);
    aReg[1] = *(const float4*)(Ap + (size_t)(aRow + 64) * K + aCol);
    bReg[0] = *(const float4*)(Bp + (size_t)bRow        * N + bCol);
    bReg[1] = *(const float4*)(Bp + (size_t)(bRow + 8)  * N + bCol);

    *(uint4*)&As[0][aRow     ][aCol] =
        make_uint4(f2tf32(aReg[0].x), f2tf32(aReg[0].y), f2tf32(aReg[0].z), f2tf32(aReg[0].w));
    *(uint4*)&As[0][aRow + 64][aCol] =
        make_uint4(f2tf32(aReg[1].x), f2tf32(aReg[1].y), f2tf32(aReg[1].z), f2tf32(aReg[1].w));
    *(uint4*)&Bs[0][bRow    ][bCol] =
        make_uint4(f2tf32(bReg[0].x), f2tf32(bReg[0].y), f2tf32(bReg[0].z), f2tf32(bReg[0].w));
    *(uint4*)&Bs[0][bRow + 8][bCol] =
        make_uint4(f2tf32(bReg[1].x), f2tf32(bReg[1].y), f2tf32(bReg[1].z), f2tf32(bReg[1].w));
    __syncthreads();

    float acc[2][8][4];
    #pragma unroll
    for (int mi = 0; mi < 2; mi++)
        #pragma unroll
        for (int ni = 0; ni < 8; ni++)
            #pragma unroll
            for (int e = 0; e < 4; e++) acc[mi][ni][e] = 0.f;

    const int nT = K / T_BK;
    for (int t = 0; t < nT; t++) {
        const int cur = t & 1;

        if (t + 1 < nT) {
            const float* Apn = Ap + (size_t)(t + 1) * T_BK;
            const float* Bpn = Bp + (size_t)(t + 1) * T_BK * N;
            aReg[0] = *(const float4*)(Apn + (size_t)aRow        * K + aCol);
            aReg[1] = *(const float4*)(Apn + (size_t)(aRow + 64) * K + aCol);
            bReg[0] = *(const float4*)(Bpn + (size_t)bRow        * N + bCol);
            bReg[1] = *(const float4*)(Bpn + (size_t)(bRow + 8)  * N + bCol);
        }

        #pragma unroll
        for (int ks = 0; ks < T_BK; ks += 8) {
            uint32_t afrag[2][4];
            uint32_t bfrag[8][2];
            const int ar = mbase + (lane >> 2);
            const int ac = ks + (lane & 3);
            #pragma unroll
            for (int mi = 0; mi < 2; mi++) {
                afrag[mi][0] = __float_as_uint(As[cur][ar + mi * 16    ][ac]);
                afrag[mi][1] = __float_as_uint(As[cur][ar + mi * 16 + 8][ac]);
                afrag[mi][2] = __float_as_uint(As[cur][ar + mi * 16    ][ac + 4]);
                afrag[mi][3] = __float_as_uint(As[cur][ar + mi * 16 + 8][ac + 4]);
            }
            const int br = ks + (lane & 3);
            const int bc = nbase + (lane >> 2);
            #pragma unroll
            for (int ni = 0; ni < 8; ni++) {
                bfrag[ni][0] = __float_as_uint(Bs[cur][br    ][bc + ni * 8]);
                bfrag[ni][1] = __float_as_uint(Bs[cur][br + 4][bc + ni * 8]);
            }
            #pragma unroll
            for (int mi = 0; mi < 2; mi++)
                #pragma unroll
                for (int ni = 0; ni < 8; ni++)
                    mma_tf32(acc[mi][ni], afrag[mi], bfrag[ni]);
        }

        if (t + 1 < nT) {
            const int nxt = cur ^ 1;
            *(uint4*)&As[nxt][aRow     ][aCol] =
                make_uint4(f2tf32(aReg[0].x), f2tf32(aReg[0].y), f2tf32(aReg[0].z), f2tf32(aReg[0].w));
            *(uint4*)&As[nxt][aRow + 64][aCol] =
                make_uint4(f2tf32(aReg[1].x), f2tf32(aReg[1].y), f2tf32(aReg[1].z), f2tf32(aReg[1].w));
            *(uint4*)&Bs[nxt][bRow    ][bCol] =
                make_uint4(f2tf32(bReg[0].x), f2tf32(bReg[0].y), f2tf32(bReg[0].z), f2tf32(bReg[0].w));
            *(uint4*)&Bs[nxt][bRow + 8][bCol] =
                make_uint4(f2tf32(bReg[1].x), f2tf32(bReg[1].y), f2tf32(bReg[1].z), f2tf32(bReg[1].w));
        }
        __syncthreads();
    }

    float* Cp = C + (size_t)(blockIdx.y * T_BM + mbase) * N + blockIdx.x * T_BN + nbase;
    #pragma unroll
    for (int mi = 0; mi < 2; mi++) {
        const int r = mi * 16 + (lane >> 2);
        #pragma unroll
        for (int ni = 0; ni < 8; ni++) {
            const int c = ni * 8 + (lane & 3) * 2;
            *(float2*)(Cp + (size_t)r       * N + c) = make_float2(acc[mi][ni][0], acc[mi][ni][1]);
            *(float2*)(Cp + (size_t)(r + 8) * N + c) = make_float2(acc[mi][ni][2], acc[mi][ni][3]);
        }
    }
}

// ----------------------------------------------------------------------------
// RoPE (in place), q and kv handled in one launch.
// ----------------------------------------------------------------------------
__global__ __launch_bounds__(256) void rope2_kernel(
    float* __restrict__ qb, float* __restrict__ kvb, const float* __restrict__ re)
{
    const size_t half = (size_t)ROWS * HEADS * 64;
    size_t idx = (size_t)blockIdx.x * blockDim.x + threadIdx.x;
    float* t;
    int ncols;
    if (idx >= half) {
        if (idx >= 2 * half) return;
        t = kvb; ncols = 2 * INNER; idx -= half;
    } else {
        t = qb; ncols = INNER;
    }
    const int d = (int)(idx & 63);
    const int h = (int)((idx >> 6) & (HEADS - 1));
    const int r = (int)(idx >> 10);
    const int n = r & (N_SEQ - 1);

    float* base = t + (size_t)r * ncols + h * DHEAD;
    const float p1 = re[n * DHEAD + d];
    const float p2 = re[n * DHEAD + d + 64];
    const float t1 = base[d];
    const float t2 = base[d + 64];
    base[d]      = t1 * cosf(p1) - t2 * sinf(p1);
    base[d + 64] = t2 * cosf(p2) + t1 * sinf(p2);
}

// ----------------------------------------------------------------------------
// Causal flash attention on tf32 tensor cores.
//   Q in smem (prescaled by 128^-0.5*log2e, tf32). KV double-buffered:
//   next tile's LDGs issue before compute, STS after a sync. ex2.approx softmax.
// ----------------------------------------------------------------------------
#define FA_BM 128
#define FA_BN 64
#define FA_STRIDE 132
#define FA_BUF (2 * FA_BN * FA_STRIDE)   // floats per (K+V) buffer
#define FA_SMEM ((FA_BM * FA_STRIDE + 2 * FA_BUF) * 4)

__global__ __launch_bounds__(256, 1) void attn_tc_kernel(
    const float* __restrict__ Q, const float* __restrict__ KV,
    float* __restrict__ O)
{
    extern __shared__ float sm[];
    float* Qs  = sm;                         // [128][132] tf32 bits (prescaled)
    float* KV0 = sm + FA_BM * FA_STRIDE;     // 2 buffers of [K|V] = [64][132] each

    const int bh = blockIdx.y;
    const int b  = bh >> 4;
    const int h  = bh & 15;
    const int qt = blockIdx.x;

    const int tid  = threadIdx.x;
    const int lane = tid & 31;
    const int warp = tid >> 5;

    const float qscale = 0.088388347648318447f * 1.4426950408889634f;

    // ---- load Q tile (prescale + tf32 at store) --------------------------
    const float* qbase = Q + ((size_t)(b * N_SEQ + qt * FA_BM)) * INNER + h * DHEAD;
    #pragma unroll
    for (int i = 0; i < 16; i++) {
        const int idx = i * 256 + tid;
        const int r = idx >> 5;
        const int c = (idx & 31) * 4;
        float4 v = *(const float4*)(qbase + (size_t)r * INNER + c);
        *(uint4*)&Qs[r * FA_STRIDE + c] = make_uint4(
            f2tf32(v.x * qscale), f2tf32(v.y * qscale),
            f2tf32(v.z * qscale), f2tf32(v.w * qscale));
    }

    // per-thread KV staging (16 LDG.128 per tile)
    const int ldr = tid >> 5;                // row block base: rows ldr, ldr+8, ...
    const int ldc = (lane) * 4;              // col 0..124
    const float* kvb = KV + ((size_t)(b * N_SEQ)) * (2 * INNER) + h * DHEAD;
    float4 kreg[8], vreg[8];

    // LDG tile 0
    #pragma unroll
    for (int i = 0; i < 8; i++) {
        const size_t gro = ((size_t)(i * 8 + ldr)) * (2 * INNER);
        kreg[i] = *(const float4*)(kvb + gro + ldc);
        vreg[i] = *(const float4*)(kvb + gro + INNER + ldc);
    }
    // STS tile 0 -> buffer 0
    {
        float* Ks = KV0;
        float* Vs = KV0 + FA_BN * FA_STRIDE;
        #pragma unroll
        for (int i = 0; i < 8; i++) {
            const int r = i * 8 + ldr;
            *(uint4*)&Ks[r * FA_STRIDE + ldc] = make_uint4(
                f2tf32(kreg[i].x), f2tf32(kreg[i].y), f2tf32(kreg[i].z), f2tf32(kreg[i].w));
            *(uint4*)&Vs[r * FA_STRIDE + ldc] = make_uint4(
                f2tf32(vreg[i].x), f2tf32(vreg[i].y), f2tf32(vreg[i].z), f2tf32(vreg[i].w));
        }
    }
    __syncthreads();

    float oacc[16][4];
    #pragma unroll
    for (int nd = 0; nd < 16; nd++)
        #pragma unroll
        for (int e = 0; e < 4; e++) oacc[nd][e] = 0.f;

    float m0 = -INFINITY, m1 = -INFINITY, l0 = 0.f, l1 = 0.f;
    const int qrow0 = qt * FA_BM + warp * 16 + (lane >> 2);
    const int warp_min_row = qt * FA_BM + warp * 16;
    const int warp_max_row = warp_min_row + 15;

    const int ntiles = 2 * qt + 2;
    for (int kt = 0; kt < ntiles; kt++) {
        float* Ks = KV0 + (kt & 1) * FA_BUF;
        float* Vs = Ks + FA_BN * FA_STRIDE;

        // prefetch next tile into regs (overlaps with compute below)
        if (kt + 1 < ntiles) {
            const float* kvn = kvb + ((size_t)((kt + 1) * FA_BN)) * (2 * INNER);
            #pragma unroll
            for (int i = 0; i < 8; i++) {
                const size_t gro = ((size_t)(i * 8 + ldr)) * (2 * INNER);
                kreg[i] = *(const float4*)(kvn + gro + ldc);
                vreg[i] = *(const float4*)(kvn + gro + INNER + ldc);
            }
        }

        if (kt * FA_BN <= warp_max_row) {
            // ---- S = Q @ K^T (log2-domain, prescaled) --------------------
            float sacc[8][4];
            #pragma unroll
            for (int ni = 0; ni < 8; ni++)
                #pragma unroll
                for (int e = 0; e < 4; e++) sacc[ni][e] = 0.f;

            #pragma unroll
            for (int ks = 0; ks < 16; ks++) {
                uint32_t a[4];
                const float* qp = &Qs[(warp * 16 + (lane >> 2)) * FA_STRIDE + ks * 8 + (lane & 3)];
                a[0] = __float_as_uint(qp[0]);
                a[1] = __float_as_uint(qp[8 * FA_STRIDE]);
                a[2] = __float_as_uint(qp[4]);
                a[3] = __float_as_uint(qp[8 * FA_STRIDE + 4]);
                #pragma unroll
                for (int ni = 0; ni < 8; ni++) {
                    uint32_t bf[2];
                    const float* kp = &Ks[(ni * 8 + (lane >> 2)) * FA_STRIDE + ks * 8 + (lane & 3)];
                    bf[0] = __float_as_uint(kp[0]);
                    bf[1] = __float_as_uint(kp[4]);
                    mma_tf32(sacc[ni], a, bf);
                }
            }

            // ---- causal mask (diagonal tiles only) -----------------------
            if (kt * FA_BN + FA_BN - 1 > warp_min_row) {
                #pragma unroll
                for (int ni = 0; ni < 8; ni++) {
                    const int cg = kt * FA_BN + ni * 8 + 2 * (lane & 3);
                    #pragma unroll
                    for (int e = 0; e < 4; e++) {
                        const int col = cg + (e & 1);
                        const int row = qrow0 + (e >> 1) * 8;
                        if (col > row) sacc[ni][e] = -INFINITY;
                    }
                }
            }

            // ---- online softmax (MUFU ex2) -------------------------------
            float rmax0 = -INFINITY, rmax1 = -INFINITY;
            #pragma unroll
            for (int ni = 0; ni < 8; ni++) {
                rmax0 = fmaxf(rmax0, fmaxf(sacc[ni][0], sacc[ni][1]));
                rmax1 = fmaxf(rmax1, fmaxf(sacc[ni][2], sacc[ni][3]));
            }
            rmax0 = fmaxf(rmax0, __shfl_xor_sync(0xffffffffu, rmax0, 1));
            rmax0 = fmaxf(rmax0, __shfl_xor_sync(0xffffffffu, rmax0, 2));
            rmax1 = fmaxf(rmax1, __shfl_xor_sync(0xffffffffu, rmax1, 1));
            rmax1 = fmaxf(rmax1, __shfl_xor_sync(0xffffffffu, rmax1, 2));

            const float mn0 = fmaxf(m0, rmax0);
            const float mn1 = fmaxf(m1, rmax1);
            const float c0 = fex2(m0 - mn0);
            const float c1 = fex2(m1 - mn1);
            float ps0 = 0.f, ps1 = 0.f;
            #pragma unroll
            for (int ni = 0; ni < 8; ni++) {
                sacc[ni][0] = fex2(sacc[ni][0] - mn0);
                sacc[ni][1] = fex2(sacc[ni][1] - mn0);
                sacc[ni][2] = fex2(sacc[ni][2] - mn1);
                sacc[ni][3] = fex2(sacc[ni][3] - mn1);
                ps0 += sacc[ni][0] + sacc[ni][1];
                ps1 += sacc[ni][2] + sacc[ni][3];
            }
            ps0 += __shfl_xor_sync(0xffffffffu, ps0, 1);
            ps0 += __shfl_xor_sync(0xffffffffu, ps0, 2);
            ps1 += __shfl_xor_sync(0xffffffffu, ps1, 1);
            ps1 += __shfl_xor_sync(0xffffffffu, ps1, 2);
            l0 = l0 * c0 + ps0;
            l1 = l1 * c1 + ps1;
            m0 = mn0;
            m1 = mn1;
            #pragma unroll
            for (int nd = 0; nd < 16; nd++) {
                oacc[nd][0] *= c0;
                oacc[nd][1] *= c0;
                oacc[nd][2] *= c1;
                oacc[nd][3] *= c1;
            }

            // ---- O += P @ V  (shuffle-transpose P acc -> A frag) ---------
            #pragma unroll
            for (int jc = 0; jc < 8; jc++) {
                const int src0 = (lane & ~3) | ((lane & 3) >> 1);
                const int src1 = src0 + 2;
                const float g00 = __shfl_sync(0xffffffffu, sacc[jc][0], src0);
                const float g01 = __shfl_sync(0xffffffffu, sacc[jc][1], src0);
                const float g10 = __shfl_sync(0xffffffffu, sacc[jc][0], src1);
                const float g11 = __shfl_sync(0xffffffffu, sacc[jc][1], src1);
                const float g20 = __shfl_sync(0xffffffffu, sacc[jc][2], src0);
                const float g21 = __shfl_sync(0xffffffffu, sacc[jc][3], src0);
                const float g30 = __shfl_sync(0xffffffffu, sacc[jc][2], src1);
                const float g31 = __shfl_sync(0xffffffffu, sacc[jc][3], src1);
                const bool odd = lane & 1;
                uint32_t a[4];
                a[0] = f2tf32(odd ? g01 : g00);
                a[1] = f2tf32(odd ? g21 : g20);
                a[2] = f2tf32(odd ? g11 : g10);
                a[3] = f2tf32(odd ? g31 : g30);
                #pragma unroll
                for (int nd = 0; nd < 16; nd++) {
                    uint32_t bf[2];
                    const float* vp = &Vs[(jc * 8 + (lane & 3)) * FA_STRIDE + nd * 8 + (lane >> 2)];
                    bf[0] = __float_as_uint(vp[0]);
                    bf[1] = __float_as_uint(vp[4 * FA_STRIDE]);
                    mma_tf32(oacc[nd], a, bf);
                }
            }
        }

        __syncthreads();                     // all compute on buffer cur done
        if (kt + 1 < ntiles) {
            float* Kn = KV0 + ((kt + 1) & 1) * FA_BUF;
            float* Vn = Kn + FA_BN * FA_STRIDE;
            #pragma unroll
            for (int i = 0; i < 8; i++) {
                const int r = i * 8 + ldr;
                *(uint4*)&Kn[r * FA_STRIDE + ldc] = make_uint4(
                    f2tf32(kreg[i].x), f2tf32(kreg[i].y), f2tf32(kreg[i].z), f2tf32(kreg[i].w));
                *(uint4*)&Vn[r * FA_STRIDE + ldc] = make_uint4(
                    f2tf32(vreg[i].x), f2tf32(vreg[i].y), f2tf32(vreg[i].z), f2tf32(vreg[i].w));
            }
            __syncthreads();                 // next buffer visible
        }
    }

    // epilogue
    const float inv0 = 1.f / l0;
    const float inv1 = 1.f / l1;
    float* ob = O + ((size_t)(b * N_SEQ + qt * FA_BM + warp * 16 + (lane >> 2))) * INNER
                  + h * DHEAD + 2 * (lane & 3);
    #pragma unroll
    for (int nd = 0; nd < 16; nd++) {
        *(float2*)(ob + nd * 8) = make_float2(oacc[nd][0] * inv0, oacc[nd][1] * inv0);
        *(float2*)(ob + (size_t)8 * INNER + nd * 8) =
            make_float2(oacc[nd][2] * inv1, oacc[nd][3] * inv1);
    }
}

// ----------------------------------------------------------------------------
// Launch
// ----------------------------------------------------------------------------
extern "C" void kernel_launch(void* const* d_in, const int* in_sizes, int n_in,
                              void* d_out, int out_size)
{
    const float* x   = (const float*)d_in[0];
    const float* re  = (const float*)d_in[1];
    const float* g   = (const float*)d_in[2];
    const float* Wq  = (const float*)d_in[3];
    const float* Wkv = (const float*)d_in[4];
    const float* Wo  = (const float*)d_in[5];
    float* out = (float*)d_out;

    float *xn, *q, *kv, *o;
    cudaGetSymbolAddress((void**)&xn, g_xn);
    cudaGetSymbolAddress((void**)&q,  g_q);
    cudaGetSymbolAddress((void**)&kv, g_kv);
    cudaGetSymbolAddress((void**)&o,  g_o);

    // 1) RMSNorm
    rmsnorm_kernel<<<ROWS, 256>>>(x, g, xn);

    // 2) projections (tf32 tensor cores)
    dim3 gq(INNER / T_BN, ROWS / T_BM);
    tf32_gemm_kernel<<<gq, 256>>>(ROWS, INNER, DIM, xn, Wq, q);
    dim3 gkv(2 * INNER / T_BN, ROWS / T_BM);
    tf32_gemm_kernel<<<gkv, 256>>>(ROWS, 2 * INNER, DIM, xn, Wkv, kv);

    // 3) RoPE on q and k (one launch)
    const size_t ropeN = 2 * (size_t)ROWS * HEADS * 64;
    const int ropeBlocks = (int)((ropeN + 255) / 256);
    rope2_kernel<<<ropeBlocks, 256>>>(q, kv, re);

    // 4) causal attention (tf32 tensor cores, double-buffered KV)
    cudaFuncSetAttribute(attn_tc_kernel,
                         cudaFuncAttributeMaxDynamicSharedMemorySize, FA_SMEM);
    dim3 ga(N_SEQ / FA_BM, B * HEADS);
    attn_tc_kernel<<<ga, 256, FA_SMEM>>>(q, kv, o);

    // 5) output projection (tf32 tensor cores)
    tf32_gemm_kernel<<<gq, 256>>>(ROWS, INNER, DIM, o, Wo, out);
}

// round 8
// speedup vs baseline: 1.0200x; 1.0200x over previous
#include <cuda_runtime.h>
#include <cuda_bf16.h>
#include <math.h>
#include <stdint.h>

// ----------------------------------------------------------------------------
// Problem constants
// ----------------------------------------------------------------------------
#define B      2
#define N_SEQ  2048
#define DIM    2048
#define HEADS  16
#define DHEAD  128
#define INNER  (HEADS * DHEAD)       // 2048
#define ROWS   (B * N_SEQ)           // 4096

// ----------------------------------------------------------------------------
// Scratch (device globals; no allocations allowed)
// ----------------------------------------------------------------------------
__device__ float g_xn[ROWS * DIM];
__device__ float g_q [ROWS * INNER];
__device__ float g_kv[ROWS * 2 * INNER];
__device__ float g_o [ROWS * INNER];

// ----------------------------------------------------------------------------
// helpers
// ----------------------------------------------------------------------------
__device__ __forceinline__ uint32_t f2tf32(float f) {
    uint32_t u;
    asm("cvt.rna.tf32.f32 %0, %1;" : "=r"(u) : "f"(f));
    return u;
}

__device__ __forceinline__ float fex2(float x) {   // hardware MUFU exp2
    float y;
    asm("ex2.approx.ftz.f32 %0, %1;" : "=f"(y) : "f"(x));
    return y;
}

__device__ __forceinline__ void mma_tf32(float* c, const uint32_t* a, const uint32_t* b) {
    asm volatile(
        "mma.sync.aligned.m16n8k8.row.col.f32.tf32.tf32.f32 "
        "{%0,%1,%2,%3},{%4,%5,%6,%7},{%8,%9},{%0,%1,%2,%3};"
        : "+f"(c[0]), "+f"(c[1]), "+f"(c[2]), "+f"(c[3])
        : "r"(a[0]), "r"(a[1]), "r"(a[2]), "r"(a[3]), "r"(b[0]), "r"(b[1]));
}

// ----------------------------------------------------------------------------
// RMSNorm
// ----------------------------------------------------------------------------
__global__ __launch_bounds__(256) void rmsnorm_kernel(
    const float* __restrict__ x, const float* __restrict__ g,
    float* __restrict__ xn)
{
    const int row = blockIdx.x;
    const float* xr = x  + (size_t)row * DIM;
    float*       xo = xn + (size_t)row * DIM;

    float ss = 0.f;
    for (int i = threadIdx.x; i < DIM; i += 256) {
        float v = xr[i];
        ss += v * v;
    }
    __shared__ float red[8];
    #pragma unroll
    for (int o = 16; o > 0; o >>= 1) ss += __shfl_xor_sync(0xffffffffu, ss, o);
    if ((threadIdx.x & 31) == 0) red[threadIdx.x >> 5] = ss;
    __syncthreads();
    if (threadIdx.x < 8) {
        float v = red[threadIdx.x];
        #pragma unroll
        for (int o = 4; o > 0; o >>= 1) v += __shfl_xor_sync(0x000000ffu, v, o);
        if (threadIdx.x == 0) red[0] = v;
    }
    __syncthreads();
    const float rms = sqrtf(red[0] * (1.f / (float)DIM));
    const float inv = 1.f / fmaxf(rms, 1e-8f);
    for (int i = threadIdx.x; i < DIM; i += 256)
        xo[i] = xr[i] * inv * g[i];
}

// ----------------------------------------------------------------------------
// TF32 tensor-core GEMM, double-buffered smem, tf32 conversion at smem store.
// (round-5 version — last measured good)
// ----------------------------------------------------------------------------
#define T_BM 128
#define T_BN 128
#define T_BK 16
#define AS_STRIDE 20
#define BS_STRIDE 136

__global__ __launch_bounds__(256, 2) void tf32_gemm_kernel(
    int M, int N, int K,
    const float* __restrict__ A, const float* __restrict__ Bm,
    float* __restrict__ C)
{
    __shared__ float As[2][T_BM][AS_STRIDE];
    __shared__ float Bs[2][T_BK][BS_STRIDE];

    const int tid  = threadIdx.x;
    const int lane = tid & 31;
    const int warp = tid >> 5;
    const int wm   = warp >> 1;
    const int wn   = warp & 1;
    const int mbase = wm * 32;
    const int nbase = wn * 64;

    const int aRow = tid >> 2;
    const int aCol = (tid & 3) * 4;
    const int bRow = tid >> 5;
    const int bCol = (tid & 31) * 4;

    const float* Ap = A  + (size_t)blockIdx.y * T_BM * K;
    const float* Bp = Bm + (size_t)blockIdx.x * T_BN;

    float4 aReg[2], bReg[2];
    aReg[0] = *(const float4*)(Ap + (size_t)aRow        * K + aCol);
    aReg[1] = *(const float4*)(Ap + (size_t)(aRow + 64) * K + aCol);
    bReg[0] = *(const float4*)(Bp + (size_t)bRow        * N + bCol);
    bReg[1] = *(const float4*)(Bp + (size_t)(bRow + 8)  * N + bCol);

    *(uint4*)&As[0][aRow     ][aCol] =
        make_uint4(f2tf32(aReg[0].x), f2tf32(aReg[0].y), f2tf32(aReg[0].z), f2tf32(aReg[0].w));
    *(uint4*)&As[0][aRow + 64][aCol] =
        make_uint4(f2tf32(aReg[1].x), f2tf32(aReg[1].y), f2tf32(aReg[1].z), f2tf32(aReg[1].w));
    *(uint4*)&Bs[0][bRow    ][bCol] =
        make_uint4(f2tf32(bReg[0].x), f2tf32(bReg[0].y), f2tf32(bReg[0].z), f2tf32(bReg[0].w));
    *(uint4*)&Bs[0][bRow + 8][bCol] =
        make_uint4(f2tf32(bReg[1].x), f2tf32(bReg[1].y), f2tf32(bReg[1].z), f2tf32(bReg[1].w));
    __syncthreads();

    float acc[2][8][4];
    #pragma unroll
    for (int mi = 0; mi < 2; mi++)
        #pragma unroll
        for (int ni = 0; ni < 8; ni++)
            #pragma unroll
            for (int e = 0; e < 4; e++) acc[mi][ni][e] = 0.f;

    const int nT = K / T_BK;
    for (int t = 0; t < nT; t++) {
        const int cur = t & 1;

        if (t + 1 < nT) {
            const float* Apn = Ap + (size_t)(t + 1) * T_BK;
            const float* Bpn = Bp + (size_t)(t + 1) * T_BK * N;
            aReg[0] = *(const float4*)(Apn + (size_t)aRow        * K + aCol);
            aReg[1] = *(const float4*)(Apn + (size_t)(aRow + 64) * K + aCol);
            bReg[0] = *(const float4*)(Bpn + (size_t)bRow        * N + bCol);
            bReg[1] = *(const float4*)(Bpn + (size_t)(bRow + 8)  * N + bCol);
        }

        #pragma unroll
        for (int ks = 0; ks < T_BK; ks += 8) {
            uint32_t afrag[2][4];
            uint32_t bfrag[8][2];
            const int ar = mbase + (lane >> 2);
            const int ac = ks + (lane & 3);
            #pragma unroll
            for (int mi = 0; mi < 2; mi++) {
                afrag[mi][0] = __float_as_uint(As[cur][ar + mi * 16    ][ac]);
                afrag[mi][1] = __float_as_uint(As[cur][ar + mi * 16 + 8][ac]);
                afrag[mi][2] = __float_as_uint(As[cur][ar + mi * 16    ][ac + 4]);
                afrag[mi][3] = __float_as_uint(As[cur][ar + mi * 16 + 8][ac + 4]);
            }
            const int br = ks + (lane & 3);
            const int bc = nbase + (lane >> 2);
            #pragma unroll
            for (int ni = 0; ni < 8; ni++) {
                bfrag[ni][0] = __float_as_uint(Bs[cur][br    ][bc + ni * 8]);
                bfrag[ni][1] = __float_as_uint(Bs[cur][br + 4][bc + ni * 8]);
            }
            #pragma unroll
            for (int mi = 0; mi < 2; mi++)
                #pragma unroll
                for (int ni = 0; ni < 8; ni++)
                    mma_tf32(acc[mi][ni], afrag[mi], bfrag[ni]);
        }

        if (t + 1 < nT) {
            const int nxt = cur ^ 1;
            *(uint4*)&As[nxt][aRow     ][aCol] =
                make_uint4(f2tf32(aReg[0].x), f2tf32(aReg[0].y), f2tf32(aReg[0].z), f2tf32(aReg[0].w));
            *(uint4*)&As[nxt][aRow + 64][aCol] =
                make_uint4(f2tf32(aReg[1].x), f2tf32(aReg[1].y), f2tf32(aReg[1].z), f2tf32(aReg[1].w));
            *(uint4*)&Bs[nxt][bRow    ][bCol] =
                make_uint4(f2tf32(bReg[0].x), f2tf32(bReg[0].y), f2tf32(bReg[0].z), f2tf32(bReg[0].w));
            *(uint4*)&Bs[nxt][bRow + 8][bCol] =
                make_uint4(f2tf32(bReg[1].x), f2tf32(bReg[1].y), f2tf32(bReg[1].z), f2tf32(bReg[1].w));
        }
        __syncthreads();
    }

    float* Cp = C + (size_t)(blockIdx.y * T_BM + mbase) * N + blockIdx.x * T_BN + nbase;
    #pragma unroll
    for (int mi = 0; mi < 2; mi++) {
        const int r = mi * 16 + (lane >> 2);
        #pragma unroll
        for (int ni = 0; ni < 8; ni++) {
            const int c = ni * 8 + (lane & 3) * 2;
            *(float2*)(Cp + (size_t)r       * N + c) = make_float2(acc[mi][ni][0], acc[mi][ni][1]);
            *(float2*)(Cp + (size_t)(r + 8) * N + c) = make_float2(acc[mi][ni][2], acc[mi][ni][3]);
        }
    }
}

// ----------------------------------------------------------------------------
// RoPE (in place), q and kv handled in one launch.
// ----------------------------------------------------------------------------
__global__ __launch_bounds__(256) void rope2_kernel(
    float* __restrict__ qb, float* __restrict__ kvb, const float* __restrict__ re)
{
    const size_t half = (size_t)ROWS * HEADS * 64;
    size_t idx = (size_t)blockIdx.x * blockDim.x + threadIdx.x;
    float* t;
    int ncols;
    if (idx >= half) {
        if (idx >= 2 * half) return;
        t = kvb; ncols = 2 * INNER; idx -= half;
    } else {
        t = qb; ncols = INNER;
    }
    const int d = (int)(idx & 63);
    const int h = (int)((idx >> 6) & (HEADS - 1));
    const int r = (int)(idx >> 10);
    const int n = r & (N_SEQ - 1);

    float* base = t + (size_t)r * ncols + h * DHEAD;
    const float p1 = re[n * DHEAD + d];
    const float p2 = re[n * DHEAD + d + 64];
    const float t1 = base[d];
    const float t2 = base[d + 64];
    base[d]      = t1 * cosf(p1) - t2 * sinf(p1);
    base[d + 64] = t2 * cosf(p2) + t1 * sinf(p2);
}

// ----------------------------------------------------------------------------
// Causal flash attention on tf32 tensor cores.
//   Register-resident Q fragments (scaled by 128^-0.5 * log2(e), tf32).
//   Smem: K,V tiles only. MUFU ex2 softmax. Mask only diagonal tiles.
// ----------------------------------------------------------------------------
#define FA_BM 128
#define FA_BN 64
#define FA_STRIDE 132
#define FA_SMEM (2 * FA_BN * FA_STRIDE * 4)

__global__ __launch_bounds__(256, 1) void attn_tc_kernel(
    const float* __restrict__ Q, const float* __restrict__ KV,
    float* __restrict__ O)
{
    extern __shared__ float sm[];
    float* Ks = sm;
    float* Vs = sm + FA_BN * FA_STRIDE;

    const int bh = blockIdx.y;
    const int b  = bh >> 4;
    const int h  = bh & 15;
    const int qt = blockIdx.x;

    const int tid  = threadIdx.x;
    const int lane = tid & 31;
    const int warp = tid >> 5;

    const float qscale = 0.088388347648318447f * 1.4426950408889634f;
    uint32_t qfrag[16][4];
    {
        const float* qb = Q + ((size_t)(b * N_SEQ + qt * FA_BM + warp * 16 + (lane >> 2))) * INNER
                            + h * DHEAD + (lane & 3);
        #pragma unroll
        for (int ks = 0; ks < 16; ks++) {
            qfrag[ks][0] = f2tf32(qb[ks * 8]                 * qscale);
            qfrag[ks][1] = f2tf32(qb[8 * INNER + ks * 8]     * qscale);
            qfrag[ks][2] = f2tf32(qb[ks * 8 + 4]             * qscale);
            qfrag[ks][3] = f2tf32(qb[8 * INNER + ks * 8 + 4] * qscale);
        }
    }

    float oacc[16][4];
    #pragma unroll
    for (int nd = 0; nd < 16; nd++)
        #pragma unroll
        for (int e = 0; e < 4; e++) oacc[nd][e] = 0.f;

    float m0 = -INFINITY, m1 = -INFINITY, l0 = 0.f, l1 = 0.f;
    const int qrow0 = qt * FA_BM + warp * 16 + (lane >> 2);
    const int warp_min_row = qt * FA_BM + warp * 16;
    const int warp_max_row = warp_min_row + 15;

    const int ntiles = 2 * qt + 2;
    for (int kt = 0; kt < ntiles; kt++) {
        __syncthreads();
        const float* kvbase = KV + ((size_t)(b * N_SEQ + kt * FA_BN)) * (2 * INNER) + h * DHEAD;
        #pragma unroll
        for (int i = 0; i < 8; i++) {
            const int idx = i * 256 + tid;
            const int r = idx >> 5;
            const int c = (idx & 31) * 4;
            float4 kv4 = *(const float4*)(kvbase + (size_t)r * (2 * INNER) + c);
            float4 vv4 = *(const float4*)(kvbase + (size_t)r * (2 * INNER) + INNER + c);
            *(uint4*)&Ks[r * FA_STRIDE + c] =
                make_uint4(f2tf32(kv4.x), f2tf32(kv4.y), f2tf32(kv4.z), f2tf32(kv4.w));
            *(uint4*)&Vs[r * FA_STRIDE + c] =
                make_uint4(f2tf32(vv4.x), f2tf32(vv4.y), f2tf32(vv4.z), f2tf32(vv4.w));
        }
        __syncthreads();

        if (kt * FA_BN > warp_max_row) continue;

        float sacc[8][4];
        #pragma unroll
        for (int ni = 0; ni < 8; ni++)
            #pragma unroll
            for (int e = 0; e < 4; e++) sacc[ni][e] = 0.f;

        #pragma unroll
        for (int ks = 0; ks < 16; ks++) {
            #pragma unroll
            for (int ni = 0; ni < 8; ni++) {
                uint32_t bf[2];
                const float* kp = &Ks[(ni * 8 + (lane >> 2)) * FA_STRIDE + ks * 8 + (lane & 3)];
                bf[0] = __float_as_uint(kp[0]);
                bf[1] = __float_as_uint(kp[4]);
                mma_tf32(sacc[ni], qfrag[ks], bf);
            }
        }

        if (kt * FA_BN + FA_BN - 1 > warp_min_row) {
            #pragma unroll
            for (int ni = 0; ni < 8; ni++) {
                const int cg = kt * FA_BN + ni * 8 + 2 * (lane & 3);
                #pragma unroll
                for (int e = 0; e < 4; e++) {
                    const int col = cg + (e & 1);
                    const int row = qrow0 + (e >> 1) * 8;
                    if (col > row) sacc[ni][e] = -INFINITY;
                }
            }
        }

        float rmax0 = -INFINITY, rmax1 = -INFINITY;
        #pragma unroll
        for (int ni = 0; ni < 8; ni++) {
            rmax0 = fmaxf(rmax0, fmaxf(sacc[ni][0], sacc[ni][1]));
            rmax1 = fmaxf(rmax1, fmaxf(sacc[ni][2], sacc[ni][3]));
        }
        rmax0 = fmaxf(rmax0, __shfl_xor_sync(0xffffffffu, rmax0, 1));
        rmax0 = fmaxf(rmax0, __shfl_xor_sync(0xffffffffu, rmax0, 2));
        rmax1 = fmaxf(rmax1, __shfl_xor_sync(0xffffffffu, rmax1, 1));
        rmax1 = fmaxf(rmax1, __shfl_xor_sync(0xffffffffu, rmax1, 2));

        const float mn0 = fmaxf(m0, rmax0);
        const float mn1 = fmaxf(m1, rmax1);
        const float c0 = fex2(m0 - mn0);
        const float c1 = fex2(m1 - mn1);
        float ps0 = 0.f, ps1 = 0.f;
        #pragma unroll
        for (int ni = 0; ni < 8; ni++) {
            sacc[ni][0] = fex2(sacc[ni][0] - mn0);
            sacc[ni][1] = fex2(sacc[ni][1] - mn0);
            sacc[ni][2] = fex2(sacc[ni][2] - mn1);
            sacc[ni][3] = fex2(sacc[ni][3] - mn1);
            ps0 += sacc[ni][0] + sacc[ni][1];
            ps1 += sacc[ni][2] + sacc[ni][3];
        }
        ps0 += __shfl_xor_sync(0xffffffffu, ps0, 1);
        ps0 += __shfl_xor_sync(0xffffffffu, ps0, 2);
        ps1 += __shfl_xor_sync(0xffffffffu, ps1, 1);
        ps1 += __shfl_xor_sync(0xffffffffu, ps1, 2);
        l0 = l0 * c0 + ps0;
        l1 = l1 * c1 + ps1;
        m0 = mn0;
        m1 = mn1;
        #pragma unroll
        for (int nd = 0; nd < 16; nd++) {
            oacc[nd][0] *= c0;
            oacc[nd][1] *= c0;
            oacc[nd][2] *= c1;
            oacc[nd][3] *= c1;
        }

        #pragma unroll
        for (int jc = 0; jc < 8; jc++) {
            const int src0 = (lane & ~3) | ((lane & 3) >> 1);
            const int src1 = src0 + 2;
            const float g00 = __shfl_sync(0xffffffffu, sacc[jc][0], src0);
            const float g01 = __shfl_sync(0xffffffffu, sacc[jc][1], src0);
            const float g10 = __shfl_sync(0xffffffffu, sacc[jc][0], src1);
            const float g11 = __shfl_sync(0xffffffffu, sacc[jc][1], src1);
            const float g20 = __shfl_sync(0xffffffffu, sacc[jc][2], src0);
            const float g21 = __shfl_sync(0xffffffffu, sacc[jc][3], src0);
            const float g30 = __shfl_sync(0xffffffffu, sacc[jc][2], src1);
            const float g31 = __shfl_sync(0xffffffffu, sacc[jc][3], src1);
            const bool odd = lane & 1;
            uint32_t a[4];
            a[0] = f2tf32(odd ? g01 : g00);
            a[1] = f2tf32(odd ? g21 : g20);
            a[2] = f2tf32(odd ? g11 : g10);
            a[3] = f2tf32(odd ? g31 : g30);
            #pragma unroll
            for (int nd = 0; nd < 16; nd++) {
                uint32_t bf[2];
                const float* vp = &Vs[(jc * 8 + (lane & 3)) * FA_STRIDE + nd * 8 + (lane >> 2)];
                bf[0] = __float_as_uint(vp[0]);
                bf[1] = __float_as_uint(vp[4 * FA_STRIDE]);
                mma_tf32(oacc[nd], a, bf);
            }
        }
    }

    const float inv0 = 1.f / l0;
    const float inv1 = 1.f / l1;
    float* ob = O + ((size_t)(b * N_SEQ + qt * FA_BM + warp * 16 + (lane >> 2))) * INNER
                  + h * DHEAD + 2 * (lane & 3);
    #pragma unroll
    for (int nd = 0; nd < 16; nd++) {
        *(float2*)(ob + nd * 8) = make_float2(oacc[nd][0] * inv0, oacc[nd][1] * inv0);
        *(float2*)(ob + (size_t)8 * INNER + nd * 8) =
            make_float2(oacc[nd][2] * inv1, oacc[nd][3] * inv1);
    }
}

// ----------------------------------------------------------------------------
// Launch
// ----------------------------------------------------------------------------
extern "C" void kernel_launch(void* const* d_in, const int* in_sizes, int n_in,
                              void* d_out, int out_size)
{
    const float* x   = (const float*)d_in[0];
    const float* re  = (const float*)d_in[1];
    const float* g   = (const float*)d_in[2];
    const float* Wq  = (const float*)d_in[3];
    const float* Wkv = (const float*)d_in[4];
    const float* Wo  = (const float*)d_in[5];
    float* out = (float*)d_out;

    float *xn, *q, *kv, *o;
    cudaGetSymbolAddress((void**)&xn, g_xn);
    cudaGetSymbolAddress((void**)&q,  g_q);
    cudaGetSymbolAddress((void**)&kv, g_kv);
    cudaGetSymbolAddress((void**)&o,  g_o);

    // 1) RMSNorm
    rmsnorm_kernel<<<ROWS, 256>>>(x, g, xn);

    // 2) projections (tf32 tensor cores)
    dim3 gq(INNER / T_BN, ROWS / T_BM);
    tf32_gemm_kernel<<<gq, 256>>>(ROWS, INNER, DIM, xn, Wq, q);
    dim3 gkv(2 * INNER / T_BN, ROWS / T_BM);
    tf32_gemm_kernel<<<gkv, 256>>>(ROWS, 2 * INNER, DIM, xn, Wkv, kv);

    // 3) RoPE on q and k (one launch)
    const size_t ropeN = 2 * (size_t)ROWS * HEADS * 64;
    const int ropeBlocks = (int)((ropeN + 255) / 256);
    rope2_kernel<<<ropeBlocks, 256>>>(q, kv, re);

    // 4) causal attention (tf32 tensor cores, MUFU ex2)
    cudaFuncSetAttribute(attn_tc_kernel,
                         cudaFuncAttributeMaxDynamicSharedMemorySize, FA_SMEM);
    dim3 ga(N_SEQ / FA_BM, B * HEADS);
    attn_tc_kernel<<<ga, 256, FA_SMEM>>>(q, kv, o);

    // 5) output projection (tf32 tensor cores)
    tf32_gemm_kernel<<<gq, 256>>>(ROWS, INNER, DIM, o, Wo, out);
}

// round 9
// speedup vs baseline: 1.5290x; 1.4991x over previous
#include <cuda_runtime.h>
#include <cuda_fp16.h>
#include <math.h>
#include <stdint.h>

// ----------------------------------------------------------------------------
// Problem constants
// ----------------------------------------------------------------------------
#define B      2
#define N_SEQ  2048
#define DIM    2048
#define HEADS  16
#define DHEAD  128
#define INNER  (HEADS * DHEAD)       // 2048
#define ROWS   (B * N_SEQ)           // 4096

// ----------------------------------------------------------------------------
// Scratch (device globals; no allocations allowed)
// ----------------------------------------------------------------------------
__device__ float g_xn[ROWS * DIM];
__device__ float g_q [ROWS * INNER];
__device__ float g_kv[ROWS * 2 * INNER];
__device__ float g_o [ROWS * INNER];

// ----------------------------------------------------------------------------
// helpers
// ----------------------------------------------------------------------------
__device__ __forceinline__ uint32_t f2h2(float lo, float hi) {   // pack {lo,hi} fp16x2
    uint32_t r;
    asm("cvt.rn.f16x2.f32 %0, %1, %2;" : "=r"(r) : "f"(hi), "f"(lo));
    return r;
}

__device__ __forceinline__ float fex2(float x) {
    float y;
    asm("ex2.approx.ftz.f32 %0, %1;" : "=f"(y) : "f"(x));
    return y;
}

__device__ __forceinline__ void mma_f16(float* c, const uint32_t* a, const uint32_t* b) {
    asm volatile(
        "mma.sync.aligned.m16n8k16.row.col.f32.f16.f16.f32 "
        "{%0,%1,%2,%3},{%4,%5,%6,%7},{%8,%9},{%0,%1,%2,%3};"
        : "+f"(c[0]), "+f"(c[1]), "+f"(c[2]), "+f"(c[3])
        : "r"(a[0]), "r"(a[1]), "r"(a[2]), "r"(a[3]), "r"(b[0]), "r"(b[1]));
}

__device__ __forceinline__ void ldm_x4(uint32_t* d, uint32_t addr) {
    asm volatile("ldmatrix.sync.aligned.m8n8.x4.shared.b16 {%0,%1,%2,%3}, [%4];"
                 : "=r"(d[0]), "=r"(d[1]), "=r"(d[2]), "=r"(d[3]) : "r"(addr));
}
__device__ __forceinline__ void ldm_x4_t(uint32_t* d, uint32_t addr) {
    asm volatile("ldmatrix.sync.aligned.m8n8.x4.trans.shared.b16 {%0,%1,%2,%3}, [%4];"
                 : "=r"(d[0]), "=r"(d[1]), "=r"(d[2]), "=r"(d[3]) : "r"(addr));
}

__device__ __forceinline__ uint32_t smem_u32(const void* p) {
    uint32_t a;
    asm("{ .reg .u64 t; cvta.to.shared.u64 t, %1; cvt.u32.u64 %0, t; }"
        : "=r"(a) : "l"(p));
    return a;
}

// ----------------------------------------------------------------------------
// RMSNorm
// ----------------------------------------------------------------------------
__global__ __launch_bounds__(256) void rmsnorm_kernel(
    const float* __restrict__ x, const float* __restrict__ g,
    float* __restrict__ xn)
{
    const int row = blockIdx.x;
    const float* xr = x  + (size_t)row * DIM;
    float*       xo = xn + (size_t)row * DIM;

    float ss = 0.f;
    for (int i = threadIdx.x; i < DIM; i += 256) {
        float v = xr[i];
        ss += v * v;
    }
    __shared__ float red[8];
    #pragma unroll
    for (int o = 16; o > 0; o >>= 1) ss += __shfl_xor_sync(0xffffffffu, ss, o);
    if ((threadIdx.x & 31) == 0) red[threadIdx.x >> 5] = ss;
    __syncthreads();
    if (threadIdx.x < 8) {
        float v = red[threadIdx.x];
        #pragma unroll
        for (int o = 4; o > 0; o >>= 1) v += __shfl_xor_sync(0x000000ffu, v, o);
        if (threadIdx.x == 0) red[0] = v;
    }
    __syncthreads();
    const float rms = sqrtf(red[0] * (1.f / (float)DIM));
    const float inv = 1.f / fmaxf(rms, 1e-8f);
    for (int i = threadIdx.x; i < DIM; i += 256)
        xo[i] = xr[i] * inv * g[i];
}

// ----------------------------------------------------------------------------
// FP16 tensor-core GEMM (m16n8k16), double-buffered, ldmatrix fragments.
// C[M,N] = A[M,K] @ B[K,N], BM=BN=128, BK=32, 8 warps, warp tile 32x64.
// ----------------------------------------------------------------------------
#define G_BK 32
#define G_SA 40     // A smem stride (halfs): rows x20 words = 4*odd -> conflict-free
#define G_SB 136    // B smem stride (halfs): rows x68 words = 4*odd -> conflict-free

__global__ __launch_bounds__(256, 2) void h16_gemm_kernel(
    int M, int N, int K,
    const float* __restrict__ A, const float* __restrict__ Bm,
    float* __restrict__ C)
{
    __shared__ __half As[2][128][G_SA];
    __shared__ __half Bs[2][G_BK][G_SB];

    const int tid  = threadIdx.x;
    const int lane = tid & 31;
    const int warp = tid >> 5;
    const int mbase = (warp >> 1) * 32;
    const int nbase = (warp & 1) * 64;

    // loader coords
    const int aRow = tid >> 1;
    const int aCol = (tid & 1) * 16;     // 16 halfs per thread per row
    const int bRow = tid >> 4;           // 0..15 (and +16)
    const int bCol = (tid & 15) * 8;

    const float* Ap = A  + (size_t)blockIdx.y * 128 * K;
    const float* Bp = Bm + (size_t)blockIdx.x * 128;

    const uint32_t asBase = smem_u32(As);
    const uint32_t bsBase = smem_u32(Bs);
    const int lrow = lane & 15;
    const int lcb  = (lane >> 4) << 3;

    uint32_t aH[8], bH[8];
    // ---- ldg+cvt tile 0 ----
    {
        const float* Ar = Ap + (size_t)aRow * K + aCol;
        #pragma unroll
        for (int i = 0; i < 4; i++) {
            float4 v = *(const float4*)(Ar + 4 * i);
            aH[2 * i]     = f2h2(v.x, v.y);
            aH[2 * i + 1] = f2h2(v.z, v.w);
        }
        #pragma unroll
        for (int rr = 0; rr < 2; rr++) {
            const float* Br = Bp + (size_t)(bRow + rr * 16) * N + bCol;
            float4 v0 = *(const float4*)(Br);
            float4 v1 = *(const float4*)(Br + 4);
            bH[rr * 4 + 0] = f2h2(v0.x, v0.y);
            bH[rr * 4 + 1] = f2h2(v0.z, v0.w);
            bH[rr * 4 + 2] = f2h2(v1.x, v1.y);
            bH[rr * 4 + 3] = f2h2(v1.z, v1.w);
        }
    }
    // ---- sts tile 0 ----
    *(uint4*)&As[0][aRow][aCol]     = make_uint4(aH[0], aH[1], aH[2], aH[3]);
    *(uint4*)&As[0][aRow][aCol + 8] = make_uint4(aH[4], aH[5], aH[6], aH[7]);
    *(uint4*)&Bs[0][bRow][bCol]      = make_uint4(bH[0], bH[1], bH[2], bH[3]);
    *(uint4*)&Bs[0][bRow + 16][bCol] = make_uint4(bH[4], bH[5], bH[6], bH[7]);
    __syncthreads();

    float acc[2][8][4];
    #pragma unroll
    for (int mi = 0; mi < 2; mi++)
        #pragma unroll
        for (int ni = 0; ni < 8; ni++)
            #pragma unroll
            for (int e = 0; e < 4; e++) acc[mi][ni][e] = 0.f;

    const int nT = K / G_BK;
    for (int t = 0; t < nT; t++) {
        const int cur = t & 1;

        if (t + 1 < nT) {
            const float* Ar = Ap + (size_t)aRow * K + (t + 1) * G_BK + aCol;
            #pragma unroll
            for (int i = 0; i < 4; i++) {
                float4 v = *(const float4*)(Ar + 4 * i);
                aH[2 * i]     = f2h2(v.x, v.y);
                aH[2 * i + 1] = f2h2(v.z, v.w);
            }
            #pragma unroll
            for (int rr = 0; rr < 2; rr++) {
                const float* Br = Bp + (size_t)((t + 1) * G_BK + bRow + rr * 16) * N + bCol;
                float4 v0 = *(const float4*)(Br);
                float4 v1 = *(const float4*)(Br + 4);
                bH[rr * 4 + 0] = f2h2(v0.x, v0.y);
                bH[rr * 4 + 1] = f2h2(v0.z, v0.w);
                bH[rr * 4 + 2] = f2h2(v1.x, v1.y);
                bH[rr * 4 + 3] = f2h2(v1.z, v1.w);
            }
        }

        const uint32_t asB = asBase + (uint32_t)cur * (128 * G_SA * 2);
        const uint32_t bsB = bsBase + (uint32_t)cur * (G_BK * G_SB * 2);
        #pragma unroll
        for (int ks = 0; ks < G_BK; ks += 16) {
            uint32_t af[2][4];
            ldm_x4(af[0], asB + (uint32_t)((mbase      + lrow) * G_SA + ks + lcb) * 2);
            ldm_x4(af[1], asB + (uint32_t)((mbase + 16 + lrow) * G_SA + ks + lcb) * 2);
            uint32_t bf[8][2];
            #pragma unroll
            for (int nb = 0; nb < 4; nb++) {
                uint32_t td[4];
                ldm_x4_t(td, bsB + (uint32_t)((ks + lrow) * G_SB + nbase + nb * 16 + lcb) * 2);
                bf[2 * nb][0]     = td[0];
                bf[2 * nb][1]     = td[1];
                bf[2 * nb + 1][0] = td[2];
                bf[2 * nb + 1][1] = td[3];
            }
            #pragma unroll
            for (int mi = 0; mi < 2; mi++)
                #pragma unroll
                for (int ni = 0; ni < 8; ni++)
                    mma_f16(acc[mi][ni], af[mi], bf[ni]);
        }

        if (t + 1 < nT) {
            const int nb = cur ^ 1;
            *(uint4*)&As[nb][aRow][aCol]     = make_uint4(aH[0], aH[1], aH[2], aH[3]);
            *(uint4*)&As[nb][aRow][aCol + 8] = make_uint4(aH[4], aH[5], aH[6], aH[7]);
            *(uint4*)&Bs[nb][bRow][bCol]      = make_uint4(bH[0], bH[1], bH[2], bH[3]);
            *(uint4*)&Bs[nb][bRow + 16][bCol] = make_uint4(bH[4], bH[5], bH[6], bH[7]);
        }
        __syncthreads();
    }

    float* Cp = C + (size_t)(blockIdx.y * 128 + mbase) * N + blockIdx.x * 128 + nbase;
    #pragma unroll
    for (int mi = 0; mi < 2; mi++) {
        const int r = mi * 16 + (lane >> 2);
        #pragma unroll
        for (int ni = 0; ni < 8; ni++) {
            const int c = ni * 8 + (lane & 3) * 2;
            *(float2*)(Cp + (size_t)r       * N + c) = make_float2(acc[mi][ni][0], acc[mi][ni][1]);
            *(float2*)(Cp + (size_t)(r + 8) * N + c) = make_float2(acc[mi][ni][2], acc[mi][ni][3]);
        }
    }
}

// ----------------------------------------------------------------------------
// RoPE (in place), q and kv handled in one launch.
// ----------------------------------------------------------------------------
__global__ __launch_bounds__(256) void rope2_kernel(
    float* __restrict__ qb, float* __restrict__ kvb, const float* __restrict__ re)
{
    const size_t half = (size_t)ROWS * HEADS * 64;
    size_t idx = (size_t)blockIdx.x * blockDim.x + threadIdx.x;
    float* t;
    int ncols;
    if (idx >= half) {
        if (idx >= 2 * half) return;
        t = kvb; ncols = 2 * INNER; idx -= half;
    } else {
        t = qb; ncols = INNER;
    }
    const int d = (int)(idx & 63);
    const int h = (int)((idx >> 6) & (HEADS - 1));
    const int r = (int)(idx >> 10);
    const int n = r & (N_SEQ - 1);

    float* base = t + (size_t)r * ncols + h * DHEAD;
    const float p1 = re[n * DHEAD + d];
    const float p2 = re[n * DHEAD + d + 64];
    const float t1 = base[d];
    const float t2 = base[d + 64];
    base[d]      = t1 * cosf(p1) - t2 * sinf(p1);
    base[d + 64] = t2 * cosf(p2) + t1 * sinf(p2);
}

// ----------------------------------------------------------------------------
// Causal flash attention on fp16 m16n8k16.
//   Q fragments in regs (prescaled by 128^-0.5*log2e). K [n][k] fp16 smem
//   (b-frags via ldmatrix non-trans). V [k][n] fp16 smem (b-frags via
//   ldmatrix.trans). P reuses QK C-frag layout directly as A-frag (no shuffles).
// ----------------------------------------------------------------------------
#define FA_BM 128
#define FA_BN 64
#define FA_SK 136     // halfs stride: x68 words = 4*odd -> conflict-free

__global__ __launch_bounds__(256, 1) void attn_h16_kernel(
    const float* __restrict__ Q, const float* __restrict__ KV,
    float* __restrict__ O)
{
    __shared__ __half Ks[FA_BN][FA_SK];   // [key j][d]
    __shared__ __half Vs[FA_BN][FA_SK];   // [key j][d]

    const int bh = blockIdx.y;
    const int b  = bh >> 4;
    const int h  = bh & 15;
    const int qt = blockIdx.x;

    const int tid  = threadIdx.x;
    const int lane = tid & 31;
    const int warp = tid >> 5;

    const uint32_t ksBase = smem_u32(Ks);
    const uint32_t vsBase = smem_u32(Vs);

    // Q fragments in registers, prescaled, fp16 pairs.
    const float qs = 0.088388347648318447f * 1.4426950408889634f;
    uint32_t qf[8][4];
    {
        const float* qb = Q + ((size_t)(b * N_SEQ + qt * FA_BM + warp * 16 + (lane >> 2))) * INNER
                            + h * DHEAD;
        #pragma unroll
        for (int ks = 0; ks < 8; ks++) {
            const int k0 = ks * 16 + 2 * (lane & 3);
            float2 v0 = *(const float2*)(qb + k0);
            float2 v1 = *(const float2*)(qb + 8 * INNER + k0);
            float2 v2 = *(const float2*)(qb + k0 + 8);
            float2 v3 = *(const float2*)(qb + 8 * INNER + k0 + 8);
            qf[ks][0] = f2h2(v0.x * qs, v0.y * qs);
            qf[ks][1] = f2h2(v1.x * qs, v1.y * qs);
            qf[ks][2] = f2h2(v2.x * qs, v2.y * qs);
            qf[ks][3] = f2h2(v3.x * qs, v3.y * qs);
        }
    }

    float oacc[16][4];
    #pragma unroll
    for (int nd = 0; nd < 16; nd++)
        #pragma unroll
        for (int e = 0; e < 4; e++) oacc[nd][e] = 0.f;

    float m0 = -INFINITY, m1 = -INFINITY, l0 = 0.f, l1 = 0.f;
    const int qrow0 = qt * FA_BM + warp * 16 + (lane >> 2);
    const int warp_min_row = qt * FA_BM + warp * 16;
    const int warp_max_row = warp_min_row + 15;

    const int ntiles = 2 * qt + 2;
    for (int kt = 0; kt < ntiles; kt++) {
        __syncthreads();
        const float* kvbase = KV + ((size_t)(b * N_SEQ + kt * FA_BN)) * (2 * INNER) + h * DHEAD;
        #pragma unroll
        for (int i = 0; i < 8; i++) {
            const int idx = i * 256 + tid;       // 0..2047
            const int r = idx >> 5;
            const int c = (idx & 31) * 4;
            float4 k4 = *(const float4*)(kvbase + (size_t)r * (2 * INNER) + c);
            float4 v4 = *(const float4*)(kvbase + (size_t)r * (2 * INNER) + INNER + c);
            *(uint2*)&Ks[r][c] = make_uint2(f2h2(k4.x, k4.y), f2h2(k4.z, k4.w));
            *(uint2*)&Vs[r][c] = make_uint2(f2h2(v4.x, v4.y), f2h2(v4.z, v4.w));
        }
        __syncthreads();

        if (kt * FA_BN > warp_max_row) continue;

        // ---- S = Q @ K^T -------------------------------------------------
        float sacc[8][4];
        #pragma unroll
        for (int ni = 0; ni < 8; ni++)
            #pragma unroll
            for (int e = 0; e < 4; e++) sacc[ni][e] = 0.f;

        #pragma unroll
        for (int ks = 0; ks < 8; ks++) {
            uint32_t kf[8][2];
            #pragma unroll
            for (int np = 0; np < 4; np++) {
                uint32_t td[4];
                // non-trans: n = np*16 + (lane&7) + ((lane>>4)<<3), k = ks*16 + (lane&8)
                ldm_x4(td, ksBase + (uint32_t)(
                    (np * 16 + (lane & 7) + ((lane >> 4) << 3)) * FA_SK
                    + ks * 16 + (lane & 8)) * 2);
                kf[2 * np][0]     = td[0];
                kf[2 * np][1]     = td[1];
                kf[2 * np + 1][0] = td[2];
                kf[2 * np + 1][1] = td[3];
            }
            #pragma unroll
            for (int ni = 0; ni < 8; ni++)
                mma_f16(sacc[ni], qf[ks], kf[ni]);
        }

        // ---- causal mask (diagonal tiles only) ---------------------------
        if (kt * FA_BN + FA_BN - 1 > warp_min_row) {
            #pragma unroll
            for (int ni = 0; ni < 8; ni++) {
                const int cg = kt * FA_BN + ni * 8 + 2 * (lane & 3);
                #pragma unroll
                for (int e = 0; e < 4; e++) {
                    const int col = cg + (e & 1);
                    const int row = qrow0 + (e >> 1) * 8;
                    if (col > row) sacc[ni][e] = -INFINITY;
                }
            }
        }

        // ---- online softmax (exp2 domain) --------------------------------
        float rmax0 = -INFINITY, rmax1 = -INFINITY;
        #pragma unroll
        for (int ni = 0; ni < 8; ni++) {
            rmax0 = fmaxf(rmax0, fmaxf(sacc[ni][0], sacc[ni][1]));
            rmax1 = fmaxf(rmax1, fmaxf(sacc[ni][2], sacc[ni][3]));
        }
        rmax0 = fmaxf(rmax0, __shfl_xor_sync(0xffffffffu, rmax0, 1));
        rmax0 = fmaxf(rmax0, __shfl_xor_sync(0xffffffffu, rmax0, 2));
        rmax1 = fmaxf(rmax1, __shfl_xor_sync(0xffffffffu, rmax1, 1));
        rmax1 = fmaxf(rmax1, __shfl_xor_sync(0xffffffffu, rmax1, 2));

        const float mn0 = fmaxf(m0, rmax0);
        const float mn1 = fmaxf(m1, rmax1);
        const float c0 = fex2(m0 - mn0);
        const float c1 = fex2(m1 - mn1);
        float ps0 = 0.f, ps1 = 0.f;
        #pragma unroll
        for (int ni = 0; ni < 8; ni++) {
            sacc[ni][0] = fex2(sacc[ni][0] - mn0);
            sacc[ni][1] = fex2(sacc[ni][1] - mn0);
            sacc[ni][2] = fex2(sacc[ni][2] - mn1);
            sacc[ni][3] = fex2(sacc[ni][3] - mn1);
            ps0 += sacc[ni][0] + sacc[ni][1];
            ps1 += sacc[ni][2] + sacc[ni][3];
        }
        ps0 += __shfl_xor_sync(0xffffffffu, ps0, 1);
        ps0 += __shfl_xor_sync(0xffffffffu, ps0, 2);
        ps1 += __shfl_xor_sync(0xffffffffu, ps1, 1);
        ps1 += __shfl_xor_sync(0xffffffffu, ps1, 2);
        l0 = l0 * c0 + ps0;
        l1 = l1 * c1 + ps1;
        m0 = mn0;
        m1 = mn1;
        #pragma unroll
        for (int nd = 0; nd < 16; nd++) {
            oacc[nd][0] *= c0;
            oacc[nd][1] *= c0;
            oacc[nd][2] *= c1;
            oacc[nd][3] *= c1;
        }

        // ---- O += P @ V  (C-frag == A-frag layout; V via ldmatrix.trans) --
        #pragma unroll
        for (int j = 0; j < 4; j++) {
            uint32_t a[4];
            a[0] = f2h2(sacc[2 * j][0],     sacc[2 * j][1]);
            a[1] = f2h2(sacc[2 * j][2],     sacc[2 * j][3]);
            a[2] = f2h2(sacc[2 * j + 1][0], sacc[2 * j + 1][1]);
            a[3] = f2h2(sacc[2 * j + 1][2], sacc[2 * j + 1][3]);
            #pragma unroll
            for (int np = 0; np < 8; np++) {
                uint32_t v[4];
                // trans: k = j*16 + (lane&15), n = np*16 + ((lane>>4)<<3)
                ldm_x4_t(v, vsBase + (uint32_t)(
                    (j * 16 + (lane & 15)) * FA_SK
                    + np * 16 + ((lane >> 4) << 3)) * 2);
                mma_f16(oacc[2 * np],     a, v);
                mma_f16(oacc[2 * np + 1], a, v + 2);
            }
        }
    }

    // epilogue
    const float inv0 = 1.f / l0;
    const float inv1 = 1.f / l1;
    float* ob = O + ((size_t)(b * N_SEQ + qt * FA_BM + warp * 16 + (lane >> 2))) * INNER
                  + h * DHEAD + 2 * (lane & 3);
    #pragma unroll
    for (int nd = 0; nd < 16; nd++) {
        *(float2*)(ob + nd * 8) = make_float2(oacc[nd][0] * inv0, oacc[nd][1] * inv0);
        *(float2*)(ob + (size_t)8 * INNER + nd * 8) =
            make_float2(oacc[nd][2] * inv1, oacc[nd][3] * inv1);
    }
}

// ----------------------------------------------------------------------------
// Launch
// ----------------------------------------------------------------------------
extern "C" void kernel_launch(void* const* d_in, const int* in_sizes, int n_in,
                              void* d_out, int out_size)
{
    const float* x   = (const float*)d_in[0];
    const float* re  = (const float*)d_in[1];
    const float* g   = (const float*)d_in[2];
    const float* Wq  = (const float*)d_in[3];
    const float* Wkv = (const float*)d_in[4];
    const float* Wo  = (const float*)d_in[5];
    float* out = (float*)d_out;

    float *xn, *q, *kv, *o;
    cudaGetSymbolAddress((void**)&xn, g_xn);
    cudaGetSymbolAddress((void**)&q,  g_q);
    cudaGetSymbolAddress((void**)&kv, g_kv);
    cudaGetSymbolAddress((void**)&o,  g_o);

    // 1) RMSNorm
    rmsnorm_kernel<<<ROWS, 256>>>(x, g, xn);

    // 2) projections (fp16 m16n8k16 tensor cores)
    dim3 gq(INNER / 128, ROWS / 128);
    h16_gemm_kernel<<<gq, 256>>>(ROWS, INNER, DIM, xn, Wq, q);
    dim3 gkv(2 * INNER / 128, ROWS / 128);
    h16_gemm_kernel<<<gkv, 256>>>(ROWS, 2 * INNER, DIM, xn, Wkv, kv);

    // 3) RoPE on q and k (one launch)
    const size_t ropeN = 2 * (size_t)ROWS * HEADS * 64;
    const int ropeBlocks = (int)((ropeN + 255) / 256);
    rope2_kernel<<<ropeBlocks, 256>>>(q, kv, re);

    // 4) causal attention (fp16 m16n8k16)
    dim3 ga(N_SEQ / FA_BM, B * HEADS);
    attn_h16_kernel<<<ga, 256>>>(q, kv, o);

    // 5) output projection (fp16 m16n8k16)
    h16_gemm_kernel<<<gq, 256>>>(ROWS, INNER, DIM, o, Wo, out);
}

// round 10
// speedup vs baseline: 1.7701x; 1.1577x over previous
#include <cuda_runtime.h>
#include <cuda_fp16.h>
#include <math.h>
#include <stdint.h>

// ----------------------------------------------------------------------------
// Problem constants
// ----------------------------------------------------------------------------
#define B      2
#define N_SEQ  2048
#define DIM    2048
#define HEADS  16
#define DHEAD  128
#define INNER  (HEADS * DHEAD)       // 2048
#define ROWS   (B * N_SEQ)           // 4096

// ----------------------------------------------------------------------------
// Scratch (device globals; no allocations allowed) — all fp16 now
// ----------------------------------------------------------------------------
__device__ __half g_xn[ROWS * DIM];
__device__ __half g_q [ROWS * INNER];
__device__ __half g_kv[ROWS * 2 * INNER];
__device__ __half g_o [ROWS * INNER];

// ----------------------------------------------------------------------------
// helpers
// ----------------------------------------------------------------------------
__device__ __forceinline__ uint32_t f2h2(float lo, float hi) {   // pack {lo,hi}
    uint32_t r;
    asm("cvt.rn.f16x2.f32 %0, %1, %2;" : "=r"(r) : "f"(hi), "f"(lo));
    return r;
}

__device__ __forceinline__ uint32_t hmul2(uint32_t a, uint32_t b) {
    uint32_t r;
    asm("mul.rn.f16x2 %0, %1, %2;" : "=r"(r) : "r"(a), "r"(b));
    return r;
}

__device__ __forceinline__ float fex2(float x) {
    float y;
    asm("ex2.approx.ftz.f32 %0, %1;" : "=f"(y) : "f"(x));
    return y;
}

__device__ __forceinline__ void mma_f16(float* c, const uint32_t* a, const uint32_t* b) {
    asm volatile(
        "mma.sync.aligned.m16n8k16.row.col.f32.f16.f16.f32 "
        "{%0,%1,%2,%3},{%4,%5,%6,%7},{%8,%9},{%0,%1,%2,%3};"
        : "+f"(c[0]), "+f"(c[1]), "+f"(c[2]), "+f"(c[3])
        : "r"(a[0]), "r"(a[1]), "r"(a[2]), "r"(a[3]), "r"(b[0]), "r"(b[1]));
}

__device__ __forceinline__ void ldm_x4(uint32_t* d, uint32_t addr) {
    asm volatile("ldmatrix.sync.aligned.m8n8.x4.shared.b16 {%0,%1,%2,%3}, [%4];"
                 : "=r"(d[0]), "=r"(d[1]), "=r"(d[2]), "=r"(d[3]) : "r"(addr));
}
__device__ __forceinline__ void ldm_x4_t(uint32_t* d, uint32_t addr) {
    asm volatile("ldmatrix.sync.aligned.m8n8.x4.trans.shared.b16 {%0,%1,%2,%3}, [%4];"
                 : "=r"(d[0]), "=r"(d[1]), "=r"(d[2]), "=r"(d[3]) : "r"(addr));
}

__device__ __forceinline__ uint32_t smem_u32(const void* p) {
    uint32_t a;
    asm("{ .reg .u64 t; cvta.to.shared.u64 t, %1; cvt.u32.u64 %0, t; }"
        : "=r"(a) : "l"(p));
    return a;
}

// ----------------------------------------------------------------------------
// RMSNorm -> fp16 output
// ----------------------------------------------------------------------------
__global__ __launch_bounds__(256) void rmsnorm_kernel(
    const float* __restrict__ x, const float* __restrict__ g,
    __half* __restrict__ xn)
{
    const int row = blockIdx.x;
    const float* xr = x  + (size_t)row * DIM;
    __half*      xo = xn + (size_t)row * DIM;

    float ss = 0.f;
    for (int i = threadIdx.x; i < DIM; i += 256) {
        float v = xr[i];
        ss += v * v;
    }
    __shared__ float red[8];
    #pragma unroll
    for (int o = 16; o > 0; o >>= 1) ss += __shfl_xor_sync(0xffffffffu, ss, o);
    if ((threadIdx.x & 31) == 0) red[threadIdx.x >> 5] = ss;
    __syncthreads();
    if (threadIdx.x < 8) {
        float v = red[threadIdx.x];
        #pragma unroll
        for (int o = 4; o > 0; o >>= 1) v += __shfl_xor_sync(0x000000ffu, v, o);
        if (threadIdx.x == 0) red[0] = v;
    }
    __syncthreads();
    const float rms = sqrtf(red[0] * (1.f / (float)DIM));
    const float inv = 1.f / fmaxf(rms, 1e-8f);
    for (int i = threadIdx.x * 2; i < DIM; i += 512) {
        float2 v = *(const float2*)(xr + i);
        *(uint32_t*)(xo + i) = f2h2(v.x * inv * g[i], v.y * inv * g[i + 1]);
    }
}

// ----------------------------------------------------------------------------
// FP16 tensor-core GEMM (m16n8k16): A fp16, B fp32 weights, C templated.
// BM=BN=128, BK=32, 8 warps, warp tile 32x64, double-buffered, ldmatrix.
// ----------------------------------------------------------------------------
#define G_BK 32
#define G_SA 40     // halfs; x20 words = 4*odd -> conflict-free
#define G_SB 136    // halfs; x68 words = 4*odd -> conflict-free

template <typename OutT>
__global__ __launch_bounds__(256, 2) void h16_gemm_kernel(
    int M, int N, int K,
    const __half* __restrict__ A, const float* __restrict__ Bm,
    OutT* __restrict__ C)
{
    __shared__ __half As[2][128][G_SA];
    __shared__ __half Bs[2][G_BK][G_SB];

    const int tid  = threadIdx.x;
    const int lane = tid & 31;
    const int warp = tid >> 5;
    const int mbase = (warp >> 1) * 32;
    const int nbase = (warp & 1) * 64;

    const int aRow = tid >> 1;
    const int aCol = (tid & 1) * 16;
    const int bRow = tid >> 4;
    const int bCol = (tid & 15) * 8;

    const __half* Ap = A  + (size_t)blockIdx.y * 128 * K;
    const float*  Bp = Bm + (size_t)blockIdx.x * 128;

    const uint32_t asBase = smem_u32(As);
    const uint32_t bsBase = smem_u32(Bs);
    const int lrow = lane & 15;
    const int lcb  = (lane >> 4) << 3;

    uint4 aU[2];
    uint32_t bH[8];
    // ---- ldg tile 0 ----
    {
        const __half* Ar = Ap + (size_t)aRow * K + aCol;
        aU[0] = *(const uint4*)(Ar);
        aU[1] = *(const uint4*)(Ar + 8);
        #pragma unroll
        for (int rr = 0; rr < 2; rr++) {
            const float* Br = Bp + (size_t)(bRow + rr * 16) * N + bCol;
            float4 v0 = *(const float4*)(Br);
            float4 v1 = *(const float4*)(Br + 4);
            bH[rr * 4 + 0] = f2h2(v0.x, v0.y);
            bH[rr * 4 + 1] = f2h2(v0.z, v0.w);
            bH[rr * 4 + 2] = f2h2(v1.x, v1.y);
            bH[rr * 4 + 3] = f2h2(v1.z, v1.w);
        }
    }
    *(uint4*)&As[0][aRow][aCol]     = aU[0];
    *(uint4*)&As[0][aRow][aCol + 8] = aU[1];
    *(uint4*)&Bs[0][bRow][bCol]      = make_uint4(bH[0], bH[1], bH[2], bH[3]);
    *(uint4*)&Bs[0][bRow + 16][bCol] = make_uint4(bH[4], bH[5], bH[6], bH[7]);
    __syncthreads();

    float acc[2][8][4];
    #pragma unroll
    for (int mi = 0; mi < 2; mi++)
        #pragma unroll
        for (int ni = 0; ni < 8; ni++)
            #pragma unroll
            for (int e = 0; e < 4; e++) acc[mi][ni][e] = 0.f;

    const int nT = K / G_BK;
    for (int t = 0; t < nT; t++) {
        const int cur = t & 1;

        if (t + 1 < nT) {
            const __half* Ar = Ap + (size_t)aRow * K + (t + 1) * G_BK + aCol;
            aU[0] = *(const uint4*)(Ar);
            aU[1] = *(const uint4*)(Ar + 8);
            #pragma unroll
            for (int rr = 0; rr < 2; rr++) {
                const float* Br = Bp + (size_t)((t + 1) * G_BK + bRow + rr * 16) * N + bCol;
                float4 v0 = *(const float4*)(Br);
                float4 v1 = *(const float4*)(Br + 4);
                bH[rr * 4 + 0] = f2h2(v0.x, v0.y);
                bH[rr * 4 + 1] = f2h2(v0.z, v0.w);
                bH[rr * 4 + 2] = f2h2(v1.x, v1.y);
                bH[rr * 4 + 3] = f2h2(v1.z, v1.w);
            }
        }

        const uint32_t asB = asBase + (uint32_t)cur * (128 * G_SA * 2);
        const uint32_t bsB = bsBase + (uint32_t)cur * (G_BK * G_SB * 2);
        #pragma unroll
        for (int ks = 0; ks < G_BK; ks += 16) {
            uint32_t af[2][4];
            ldm_x4(af[0], asB + (uint32_t)((mbase      + lrow) * G_SA + ks + lcb) * 2);
            ldm_x4(af[1], asB + (uint32_t)((mbase + 16 + lrow) * G_SA + ks + lcb) * 2);
            uint32_t bf[8][2];
            #pragma unroll
            for (int nb = 0; nb < 4; nb++) {
                uint32_t td[4];
                ldm_x4_t(td, bsB + (uint32_t)((ks + lrow) * G_SB + nbase + nb * 16 + lcb) * 2);
                bf[2 * nb][0]     = td[0];
                bf[2 * nb][1]     = td[1];
                bf[2 * nb + 1][0] = td[2];
                bf[2 * nb + 1][1] = td[3];
            }
            #pragma unroll
            for (int mi = 0; mi < 2; mi++)
                #pragma unroll
                for (int ni = 0; ni < 8; ni++)
                    mma_f16(acc[mi][ni], af[mi], bf[ni]);
        }

        if (t + 1 < nT) {
            const int nb = cur ^ 1;
            *(uint4*)&As[nb][aRow][aCol]     = aU[0];
            *(uint4*)&As[nb][aRow][aCol + 8] = aU[1];
            *(uint4*)&Bs[nb][bRow][bCol]      = make_uint4(bH[0], bH[1], bH[2], bH[3]);
            *(uint4*)&Bs[nb][bRow + 16][bCol] = make_uint4(bH[4], bH[5], bH[6], bH[7]);
        }
        __syncthreads();
    }

    OutT* Cp = C + (size_t)(blockIdx.y * 128 + mbase) * N + blockIdx.x * 128 + nbase;
    #pragma unroll
    for (int mi = 0; mi < 2; mi++) {
        const int r = mi * 16 + (lane >> 2);
        #pragma unroll
        for (int ni = 0; ni < 8; ni++) {
            const int c = ni * 8 + (lane & 3) * 2;
            if constexpr (sizeof(OutT) == 2) {
                *(uint32_t*)(Cp + (size_t)r       * N + c) = f2h2(acc[mi][ni][0], acc[mi][ni][1]);
                *(uint32_t*)(Cp + (size_t)(r + 8) * N + c) = f2h2(acc[mi][ni][2], acc[mi][ni][3]);
            } else {
                *(float2*)(Cp + (size_t)r       * N + c) = make_float2(acc[mi][ni][0], acc[mi][ni][1]);
                *(float2*)(Cp + (size_t)(r + 8) * N + c) = make_float2(acc[mi][ni][2], acc[mi][ni][3]);
            }
        }
    }
}

// ----------------------------------------------------------------------------
// RoPE (in place, fp16 buffers), q and kv handled in one launch.
// ----------------------------------------------------------------------------
__global__ __launch_bounds__(256) void rope2_kernel(
    __half* __restrict__ qb, __half* __restrict__ kvb, const float* __restrict__ re)
{
    const size_t half_n = (size_t)ROWS * HEADS * 64;
    size_t idx = (size_t)blockIdx.x * blockDim.x + threadIdx.x;
    __half* t;
    int ncols;
    if (idx >= half_n) {
        if (idx >= 2 * half_n) return;
        t = kvb; ncols = 2 * INNER; idx -= half_n;
    } else {
        t = qb; ncols = INNER;
    }
    const int d = (int)(idx & 63);
    const int h = (int)((idx >> 6) & (HEADS - 1));
    const int r = (int)(idx >> 10);
    const int n = r & (N_SEQ - 1);

    __half* base = t + (size_t)r * ncols + h * DHEAD;
    const float p1 = re[n * DHEAD + d];
    const float p2 = re[n * DHEAD + d + 64];
    const float t1 = __half2float(base[d]);
    const float t2 = __half2float(base[d + 64]);
    base[d]      = __float2half(t1 * cosf(p1) - t2 * sinf(p1));
    base[d + 64] = __float2half(t2 * cosf(p2) + t1 * sinf(p2));
}

// ----------------------------------------------------------------------------
// Causal flash attention, fp16 m16n8k16, fp16 I/O.
// ----------------------------------------------------------------------------
#define FA_BM 128
#define FA_BN 64
#define FA_SK 136

__global__ __launch_bounds__(256, 1) void attn_h16_kernel(
    const __half* __restrict__ Q, const __half* __restrict__ KV,
    __half* __restrict__ O)
{
    __shared__ __half Ks[FA_BN][FA_SK];
    __shared__ __half Vs[FA_BN][FA_SK];

    const int bh = blockIdx.y;
    const int b  = bh >> 4;
    const int h  = bh & 15;
    const int qt = blockIdx.x;

    const int tid  = threadIdx.x;
    const int lane = tid & 31;
    const int warp = tid >> 5;

    const uint32_t ksBase = smem_u32(Ks);
    const uint32_t vsBase = smem_u32(Vs);

    // Q fragments (half2 loads, prescaled in fp16)
    const float qsf = 0.088388347648318447f * 1.4426950408889634f;
    const uint32_t qs2 = f2h2(qsf, qsf);
    uint32_t qf[8][4];
    {
        const __half* qb = Q + ((size_t)(b * N_SEQ + qt * FA_BM + warp * 16 + (lane >> 2))) * INNER
                             + h * DHEAD;
        #pragma unroll
        for (int ks = 0; ks < 8; ks++) {
            const int k0 = ks * 16 + 2 * (lane & 3);
            qf[ks][0] = hmul2(*(const uint32_t*)(qb + k0), qs2);
            qf[ks][1] = hmul2(*(const uint32_t*)(qb + 8 * INNER + k0), qs2);
            qf[ks][2] = hmul2(*(const uint32_t*)(qb + k0 + 8), qs2);
            qf[ks][3] = hmul2(*(const uint32_t*)(qb + 8 * INNER + k0 + 8), qs2);
        }
    }

    float oacc[16][4];
    #pragma unroll
    for (int nd = 0; nd < 16; nd++)
        #pragma unroll
        for (int e = 0; e < 4; e++) oacc[nd][e] = 0.f;

    float m0 = -INFINITY, m1 = -INFINITY, l0 = 0.f, l1 = 0.f;
    const int qrow0 = qt * FA_BM + warp * 16 + (lane >> 2);
    const int warp_min_row = qt * FA_BM + warp * 16;
    const int warp_max_row = warp_min_row + 15;

    const int ntiles = 2 * qt + 2;
    for (int kt = 0; kt < ntiles; kt++) {
        __syncthreads();
        const __half* kvbase = KV + ((size_t)(b * N_SEQ + kt * FA_BN)) * (2 * INNER) + h * DHEAD;
        #pragma unroll
        for (int i = 0; i < 4; i++) {
            const int idx = i * 256 + tid;       // 0..1023
            const int r = idx >> 4;
            const int c = (idx & 15) * 8;
            *(uint4*)&Ks[r][c] = *(const uint4*)(kvbase + (size_t)r * (2 * INNER) + c);
            *(uint4*)&Vs[r][c] = *(const uint4*)(kvbase + (size_t)r * (2 * INNER) + INNER + c);
        }
        __syncthreads();

        if (kt * FA_BN > warp_max_row) continue;

        // ---- S = Q @ K^T -------------------------------------------------
        float sacc[8][4];
        #pragma unroll
        for (int ni = 0; ni < 8; ni++)
            #pragma unroll
            for (int e = 0; e < 4; e++) sacc[ni][e] = 0.f;

        #pragma unroll
        for (int ks = 0; ks < 8; ks++) {
            uint32_t kf[8][2];
            #pragma unroll
            for (int np = 0; np < 4; np++) {
                uint32_t td[4];
                ldm_x4(td, ksBase + (uint32_t)(
                    (np * 16 + (lane & 7) + ((lane >> 4) << 3)) * FA_SK
                    + ks * 16 + (lane & 8)) * 2);
                kf[2 * np][0]     = td[0];
                kf[2 * np][1]     = td[1];
                kf[2 * np + 1][0] = td[2];
                kf[2 * np + 1][1] = td[3];
            }
            #pragma unroll
            for (int ni = 0; ni < 8; ni++)
                mma_f16(sacc[ni], qf[ks], kf[ni]);
        }

        // ---- causal mask (diagonal tiles only) ---------------------------
        if (kt * FA_BN + FA_BN - 1 > warp_min_row) {
            #pragma unroll
            for (int ni = 0; ni < 8; ni++) {
                const int cg = kt * FA_BN + ni * 8 + 2 * (lane & 3);
                #pragma unroll
                for (int e = 0; e < 4; e++) {
                    const int col = cg + (e & 1);
                    const int row = qrow0 + (e >> 1) * 8;
                    if (col > row) sacc[ni][e] = -INFINITY;
                }
            }
        }

        // ---- online softmax (exp2 domain) --------------------------------
        float rmax0 = -INFINITY, rmax1 = -INFINITY;
        #pragma unroll
        for (int ni = 0; ni < 8; ni++) {
            rmax0 = fmaxf(rmax0, fmaxf(sacc[ni][0], sacc[ni][1]));
            rmax1 = fmaxf(rmax1, fmaxf(sacc[ni][2], sacc[ni][3]));
        }
        rmax0 = fmaxf(rmax0, __shfl_xor_sync(0xffffffffu, rmax0, 1));
        rmax0 = fmaxf(rmax0, __shfl_xor_sync(0xffffffffu, rmax0, 2));
        rmax1 = fmaxf(rmax1, __shfl_xor_sync(0xffffffffu, rmax1, 1));
        rmax1 = fmaxf(rmax1, __shfl_xor_sync(0xffffffffu, rmax1, 2));

        const float mn0 = fmaxf(m0, rmax0);
        const float mn1 = fmaxf(m1, rmax1);
        const float c0 = fex2(m0 - mn0);
        const float c1 = fex2(m1 - mn1);
        float ps0 = 0.f, ps1 = 0.f;
        #pragma unroll
        for (int ni = 0; ni < 8; ni++) {
            sacc[ni][0] = fex2(sacc[ni][0] - mn0);
            sacc[ni][1] = fex2(sacc[ni][1] - mn0);
            sacc[ni][2] = fex2(sacc[ni][2] - mn1);
            sacc[ni][3] = fex2(sacc[ni][3] - mn1);
            ps0 += sacc[ni][0] + sacc[ni][1];
            ps1 += sacc[ni][2] + sacc[ni][3];
        }
        ps0 += __shfl_xor_sync(0xffffffffu, ps0, 1);
        ps0 += __shfl_xor_sync(0xffffffffu, ps0, 2);
        ps1 += __shfl_xor_sync(0xffffffffu, ps1, 1);
        ps1 += __shfl_xor_sync(0xffffffffu, ps1, 2);
        l0 = l0 * c0 + ps0;
        l1 = l1 * c1 + ps1;
        m0 = mn0;
        m1 = mn1;
        #pragma unroll
        for (int nd = 0; nd < 16; nd++) {
            oacc[nd][0] *= c0;
            oacc[nd][1] *= c0;
            oacc[nd][2] *= c1;
            oacc[nd][3] *= c1;
        }

        // ---- O += P @ V  (C-frag == A-frag layout) -----------------------
        #pragma unroll
        for (int j = 0; j < 4; j++) {
            uint32_t a[4];
            a[0] = f2h2(sacc[2 * j][0],     sacc[2 * j][1]);
            a[1] = f2h2(sacc[2 * j][2],     sacc[2 * j][3]);
            a[2] = f2h2(sacc[2 * j + 1][0], sacc[2 * j + 1][1]);
            a[3] = f2h2(sacc[2 * j + 1][2], sacc[2 * j + 1][3]);
            #pragma unroll
            for (int np = 0; np < 8; np++) {
                uint32_t v[4];
                ldm_x4_t(v, vsBase + (uint32_t)(
                    (j * 16 + (lane & 15)) * FA_SK
                    + np * 16 + ((lane >> 4) << 3)) * 2);
                mma_f16(oacc[2 * np],     a, v);
                mma_f16(oacc[2 * np + 1], a, v + 2);
            }
        }
    }

    // epilogue (fp16 out)
    const float inv0 = 1.f / l0;
    const float inv1 = 1.f / l1;
    __half* ob = O + ((size_t)(b * N_SEQ + qt * FA_BM + warp * 16 + (lane >> 2))) * INNER
                   + h * DHEAD + 2 * (lane & 3);
    #pragma unroll
    for (int nd = 0; nd < 16; nd++) {
        *(uint32_t*)(ob + nd * 8) = f2h2(oacc[nd][0] * inv0, oacc[nd][1] * inv0);
        *(uint32_t*)(ob + (size_t)8 * INNER + nd * 8) =
            f2h2(oacc[nd][2] * inv1, oacc[nd][3] * inv1);
    }
}

// ----------------------------------------------------------------------------
// Launch
// ----------------------------------------------------------------------------
extern "C" void kernel_launch(void* const* d_in, const int* in_sizes, int n_in,
                              void* d_out, int out_size)
{
    const float* x   = (const float*)d_in[0];
    const float* re  = (const float*)d_in[1];
    const float* g   = (const float*)d_in[2];
    const float* Wq  = (const float*)d_in[3];
    const float* Wkv = (const float*)d_in[4];
    const float* Wo  = (const float*)d_in[5];
    float* out = (float*)d_out;

    __half *xn, *q, *kv, *o;
    cudaGetSymbolAddress((void**)&xn, g_xn);
    cudaGetSymbolAddress((void**)&q,  g_q);
    cudaGetSymbolAddress((void**)&kv, g_kv);
    cudaGetSymbolAddress((void**)&o,  g_o);

    // 1) RMSNorm (fp16 out)
    rmsnorm_kernel<<<ROWS, 256>>>(x, g, xn);

    // 2) projections (fp16 in, fp16 out)
    dim3 gq(INNER / 128, ROWS / 128);
    h16_gemm_kernel<__half><<<gq, 256>>>(ROWS, INNER, DIM, xn, Wq, q);
    dim3 gkv(2 * INNER / 128, ROWS / 128);
    h16_gemm_kernel<__half><<<gkv, 256>>>(ROWS, 2 * INNER, DIM, xn, Wkv, kv);

    // 3) RoPE on q and k (one launch, fp16)
    const size_t ropeN = 2 * (size_t)ROWS * HEADS * 64;
    const int ropeBlocks = (int)((ropeN + 255) / 256);
    rope2_kernel<<<ropeBlocks, 256>>>(q, kv, re);

    // 4) causal attention (fp16 in/out)
    dim3 ga(N_SEQ / FA_BM, B * HEADS);
    attn_h16_kernel<<<ga, 256>>>(q, kv, o);

    // 5) output projection (fp16 in, fp32 out)
    h16_gemm_kernel<float><<<gq, 256>>>(ROWS, INNER, DIM, o, Wo, out);
}

// round 11
// speedup vs baseline: 2.0628x; 1.1653x over previous
#include <cuda_runtime.h>
#include <cuda_fp16.h>
#include <math.h>
#include <stdint.h>

// ----------------------------------------------------------------------------
// Problem constants
// ----------------------------------------------------------------------------
#define B      2
#define N_SEQ  2048
#define DIM    2048
#define HEADS  16
#define DHEAD  128
#define INNER  (HEADS * DHEAD)       // 2048
#define ROWS   (B * N_SEQ)           // 4096
#define NQKV   (3 * INNER)           // 6144 fused projection width

// ----------------------------------------------------------------------------
// Scratch (device globals; no allocations allowed)
// ----------------------------------------------------------------------------
__device__ __half g_xn  [ROWS * DIM];        // normalized input (fp16)
__device__ __half g_qkv [ROWS * NQKV];       // fused q|k|v       (fp16)
__device__ __half g_o   [ROWS * INNER];      // attention output  (fp16)
__device__ __half g_wqkv[DIM * NQKV];        // fused Wq|Wkv      (fp16)
__device__ __half g_wo  [INNER * DIM];       // Wo                (fp16)

// ----------------------------------------------------------------------------
// helpers
// ----------------------------------------------------------------------------
__device__ __forceinline__ uint32_t f2h2(float lo, float hi) {
    uint32_t r;
    asm("cvt.rn.f16x2.f32 %0, %1, %2;" : "=r"(r) : "f"(hi), "f"(lo));
    return r;
}

__device__ __forceinline__ uint32_t hmul2(uint32_t a, uint32_t b) {
    uint32_t r;
    asm("mul.rn.f16x2 %0, %1, %2;" : "=r"(r) : "r"(a), "r"(b));
    return r;
}

__device__ __forceinline__ float fex2(float x) {
    float y;
    asm("ex2.approx.ftz.f32 %0, %1;" : "=f"(y) : "f"(x));
    return y;
}

__device__ __forceinline__ void mma_f16(float* c, const uint32_t* a, const uint32_t* b) {
    asm volatile(
        "mma.sync.aligned.m16n8k16.row.col.f32.f16.f16.f32 "
        "{%0,%1,%2,%3},{%4,%5,%6,%7},{%8,%9},{%0,%1,%2,%3};"
        : "+f"(c[0]), "+f"(c[1]), "+f"(c[2]), "+f"(c[3])
        : "r"(a[0]), "r"(a[1]), "r"(a[2]), "r"(a[3]), "r"(b[0]), "r"(b[1]));
}

__device__ __forceinline__ void ldm_x4(uint32_t* d, uint32_t addr) {
    asm volatile("ldmatrix.sync.aligned.m8n8.x4.shared.b16 {%0,%1,%2,%3}, [%4];"
                 : "=r"(d[0]), "=r"(d[1]), "=r"(d[2]), "=r"(d[3]) : "r"(addr));
}
__device__ __forceinline__ void ldm_x4_t(uint32_t* d, uint32_t addr) {
    asm volatile("ldmatrix.sync.aligned.m8n8.x4.trans.shared.b16 {%0,%1,%2,%3}, [%4];"
                 : "=r"(d[0]), "=r"(d[1]), "=r"(d[2]), "=r"(d[3]) : "r"(addr));
}

__device__ __forceinline__ uint32_t smem_u32(const void* p) {
    uint32_t a;
    asm("{ .reg .u64 t; cvta.to.shared.u64 t, %1; cvt.u32.u64 %0, t; }"
        : "=r"(a) : "l"(p));
    return a;
}

// ----------------------------------------------------------------------------
// Weight fp32 -> fp16 conversion (with column remap into fused buffers)
// ----------------------------------------------------------------------------
__global__ __launch_bounds__(256) void cvtw_kernel(
    const float* __restrict__ src, __half* __restrict__ dst,
    int src_ncols, int dst_ncols, int col_off, int n)
{
    const int idx = (blockIdx.x * 256 + threadIdx.x) * 4;
    if (idx >= n) return;
    const int r = idx / src_ncols;
    const int c = idx - r * src_ncols;
    float4 v = *(const float4*)(src + idx);
    *(uint2*)(dst + (size_t)r * dst_ncols + col_off + c) =
        make_uint2(f2h2(v.x, v.y), f2h2(v.z, v.w));
}

// ----------------------------------------------------------------------------
// RMSNorm -> fp16 output
// ----------------------------------------------------------------------------
__global__ __launch_bounds__(256) void rmsnorm_kernel(
    const float* __restrict__ x, const float* __restrict__ g,
    __half* __restrict__ xn)
{
    const int row = blockIdx.x;
    const float* xr = x  + (size_t)row * DIM;
    __half*      xo = xn + (size_t)row * DIM;

    float ss = 0.f;
    for (int i = threadIdx.x; i < DIM; i += 256) {
        float v = xr[i];
        ss += v * v;
    }
    __shared__ float red[8];
    #pragma unroll
    for (int o = 16; o > 0; o >>= 1) ss += __shfl_xor_sync(0xffffffffu, ss, o);
    if ((threadIdx.x & 31) == 0) red[threadIdx.x >> 5] = ss;
    __syncthreads();
    if (threadIdx.x < 8) {
        float v = red[threadIdx.x];
        #pragma unroll
        for (int o = 4; o > 0; o >>= 1) v += __shfl_xor_sync(0x000000ffu, v, o);
        if (threadIdx.x == 0) red[0] = v;
    }
    __syncthreads();
    const float rms = sqrtf(red[0] * (1.f / (float)DIM));
    const float inv = 1.f / fmaxf(rms, 1e-8f);
    for (int i = threadIdx.x * 2; i < DIM; i += 512) {
        float2 v = *(const float2*)(xr + i);
        *(uint32_t*)(xo + i) = f2h2(v.x * inv * g[i], v.y * inv * g[i + 1]);
    }
}

// ----------------------------------------------------------------------------
// FP16 tensor-core GEMM (m16n8k16): A fp16, B fp16, C templated.
// BM=BN=128, BK=32, 8 warps, warp tile 32x64, double-buffered, ldmatrix.
// ----------------------------------------------------------------------------
#define G_BK 32
#define G_SA 40
#define G_SB 136

template <typename OutT>
__global__ __launch_bounds__(256, 2) void h16_gemm_kernel(
    int M, int N, int K,
    const __half* __restrict__ A, const __half* __restrict__ Bm,
    OutT* __restrict__ C)
{
    __shared__ __half As[2][128][G_SA];
    __shared__ __half Bs[2][G_BK][G_SB];

    const int tid  = threadIdx.x;
    const int lane = tid & 31;
    const int warp = tid >> 5;
    const int mbase = (warp >> 1) * 32;
    const int nbase = (warp & 1) * 64;

    const int aRow = tid >> 1;
    const int aCol = (tid & 1) * 16;
    const int bRow = tid >> 4;
    const int bCol = (tid & 15) * 8;

    const __half* Ap = A  + (size_t)blockIdx.y * 128 * K;
    const __half* Bp = Bm + (size_t)blockIdx.x * 128;

    const uint32_t asBase = smem_u32(As);
    const uint32_t bsBase = smem_u32(Bs);
    const int lrow = lane & 15;
    const int lcb  = (lane >> 4) << 3;

    uint4 aU[2], bU[2];
    {
        const __half* Ar = Ap + (size_t)aRow * K + aCol;
        aU[0] = *(const uint4*)(Ar);
        aU[1] = *(const uint4*)(Ar + 8);
        bU[0] = *(const uint4*)(Bp + (size_t)bRow        * N + bCol);
        bU[1] = *(const uint4*)(Bp + (size_t)(bRow + 16) * N + bCol);
    }
    *(uint4*)&As[0][aRow][aCol]      = aU[0];
    *(uint4*)&As[0][aRow][aCol + 8]  = aU[1];
    *(uint4*)&Bs[0][bRow][bCol]      = bU[0];
    *(uint4*)&Bs[0][bRow + 16][bCol] = bU[1];
    __syncthreads();

    float acc[2][8][4];
    #pragma unroll
    for (int mi = 0; mi < 2; mi++)
        #pragma unroll
        for (int ni = 0; ni < 8; ni++)
            #pragma unroll
            for (int e = 0; e < 4; e++) acc[mi][ni][e] = 0.f;

    const int nT = K / G_BK;
    for (int t = 0; t < nT; t++) {
        const int cur = t & 1;

        if (t + 1 < nT) {
            const __half* Ar = Ap + (size_t)aRow * K + (t + 1) * G_BK + aCol;
            aU[0] = *(const uint4*)(Ar);
            aU[1] = *(const uint4*)(Ar + 8);
            const __half* Br = Bp + (size_t)((t + 1) * G_BK) * N;
            bU[0] = *(const uint4*)(Br + (size_t)bRow        * N + bCol);
            bU[1] = *(const uint4*)(Br + (size_t)(bRow + 16) * N + bCol);
        }

        const uint32_t asB = asBase + (uint32_t)cur * (128 * G_SA * 2);
        const uint32_t bsB = bsBase + (uint32_t)cur * (G_BK * G_SB * 2);
        #pragma unroll
        for (int ks = 0; ks < G_BK; ks += 16) {
            uint32_t af[2][4];
            ldm_x4(af[0], asB + (uint32_t)((mbase      + lrow) * G_SA + ks + lcb) * 2);
            ldm_x4(af[1], asB + (uint32_t)((mbase + 16 + lrow) * G_SA + ks + lcb) * 2);
            uint32_t bf[8][2];
            #pragma unroll
            for (int nb = 0; nb < 4; nb++) {
                uint32_t td[4];
                ldm_x4_t(td, bsB + (uint32_t)((ks + lrow) * G_SB + nbase + nb * 16 + lcb) * 2);
                bf[2 * nb][0]     = td[0];
                bf[2 * nb][1]     = td[1];
                bf[2 * nb + 1][0] = td[2];
                bf[2 * nb + 1][1] = td[3];
            }
            #pragma unroll
            for (int mi = 0; mi < 2; mi++)
                #pragma unroll
                for (int ni = 0; ni < 8; ni++)
                    mma_f16(acc[mi][ni], af[mi], bf[ni]);
        }

        if (t + 1 < nT) {
            const int nb = cur ^ 1;
            *(uint4*)&As[nb][aRow][aCol]      = aU[0];
            *(uint4*)&As[nb][aRow][aCol + 8]  = aU[1];
            *(uint4*)&Bs[nb][bRow][bCol]      = bU[0];
            *(uint4*)&Bs[nb][bRow + 16][bCol] = bU[1];
        }
        __syncthreads();
    }

    OutT* Cp = C + (size_t)(blockIdx.y * 128 + mbase) * N + blockIdx.x * 128 + nbase;
    #pragma unroll
    for (int mi = 0; mi < 2; mi++) {
        const int r = mi * 16 + (lane >> 2);
        #pragma unroll
        for (int ni = 0; ni < 8; ni++) {
            const int c = ni * 8 + (lane & 3) * 2;
            if constexpr (sizeof(OutT) == 2) {
                *(uint32_t*)(Cp + (size_t)r       * N + c) = f2h2(acc[mi][ni][0], acc[mi][ni][1]);
                *(uint32_t*)(Cp + (size_t)(r + 8) * N + c) = f2h2(acc[mi][ni][2], acc[mi][ni][3]);
            } else {
                *(float2*)(Cp + (size_t)r       * N + c) = make_float2(acc[mi][ni][0], acc[mi][ni][1]);
                *(float2*)(Cp + (size_t)(r + 8) * N + c) = make_float2(acc[mi][ni][2], acc[mi][ni][3]);
            }
        }
    }
}

// ----------------------------------------------------------------------------
// RoPE on q (cols 0..2047) and k (cols 2048..4095) of fused qkv, in place.
// ----------------------------------------------------------------------------
__global__ __launch_bounds__(256) void rope2_kernel(
    __half* __restrict__ qkv, const float* __restrict__ re)
{
    const size_t half_n = (size_t)ROWS * HEADS * 64;
    size_t idx = (size_t)blockIdx.x * blockDim.x + threadIdx.x;
    int coff;
    if (idx >= half_n) {
        if (idx >= 2 * half_n) return;
        idx -= half_n;
        coff = INNER;          // k block
    } else {
        coff = 0;              // q block
    }
    const int d = (int)(idx & 63);
    const int h = (int)((idx >> 6) & (HEADS - 1));
    const int r = (int)(idx >> 10);
    const int n = r & (N_SEQ - 1);

    __half* base = qkv + (size_t)r * NQKV + coff + h * DHEAD;
    const float p1 = re[n * DHEAD + d];
    const float p2 = re[n * DHEAD + d + 64];
    const float t1 = __half2float(base[d]);
    const float t2 = __half2float(base[d + 64]);
    base[d]      = __float2half(t1 * cosf(p1) - t2 * sinf(p1));
    base[d + 64] = __float2half(t2 * cosf(p2) + t1 * sinf(p2));
}

// ----------------------------------------------------------------------------
// Causal flash attention, fp16 m16n8k16, fused-qkv input.
// qt reversed (heavy CTAs first) for wave-tail balance.
// ----------------------------------------------------------------------------
#define FA_BM 128
#define FA_BN 64
#define FA_SK 136

__global__ __launch_bounds__(256, 1) void attn_h16_kernel(
    const __half* __restrict__ QKV, __half* __restrict__ O)
{
    __shared__ __half Ks[FA_BN][FA_SK];
    __shared__ __half Vs[FA_BN][FA_SK];

    const int bh = blockIdx.y;
    const int b  = bh >> 4;
    const int h  = bh & 15;
    const int qt = gridDim.x - 1 - blockIdx.x;   // heavy tiles first

    const int tid  = threadIdx.x;
    const int lane = tid & 31;
    const int warp = tid >> 5;

    const uint32_t ksBase = smem_u32(Ks);
    const uint32_t vsBase = smem_u32(Vs);

    // Q fragments (half2 loads from fused buffer, prescaled in fp16)
    const float qsf = 0.088388347648318447f * 1.4426950408889634f;
    const uint32_t qs2 = f2h2(qsf, qsf);
    uint32_t qf[8][4];
    {
        const __half* qb = QKV + ((size_t)(b * N_SEQ + qt * FA_BM + warp * 16 + (lane >> 2))) * NQKV
                               + h * DHEAD;
        #pragma unroll
        for (int ks = 0; ks < 8; ks++) {
            const int k0 = ks * 16 + 2 * (lane & 3);
            qf[ks][0] = hmul2(*(const uint32_t*)(qb + k0), qs2);
            qf[ks][1] = hmul2(*(const uint32_t*)(qb + 8 * NQKV + k0), qs2);
            qf[ks][2] = hmul2(*(const uint32_t*)(qb + k0 + 8), qs2);
            qf[ks][3] = hmul2(*(const uint32_t*)(qb + 8 * NQKV + k0 + 8), qs2);
        }
    }

    float oacc[16][4];
    #pragma unroll
    for (int nd = 0; nd < 16; nd++)
        #pragma unroll
        for (int e = 0; e < 4; e++) oacc[nd][e] = 0.f;

    float m0 = -INFINITY, m1 = -INFINITY, l0 = 0.f, l1 = 0.f;
    const int qrow0 = qt * FA_BM + warp * 16 + (lane >> 2);
    const int warp_min_row = qt * FA_BM + warp * 16;
    const int warp_max_row = warp_min_row + 15;

    const int ntiles = 2 * qt + 2;
    for (int kt = 0; kt < ntiles; kt++) {
        __syncthreads();
        const __half* kvbase = QKV + ((size_t)(b * N_SEQ + kt * FA_BN)) * NQKV
                                   + INNER + h * DHEAD;    // K block
        #pragma unroll
        for (int i = 0; i < 4; i++) {
            const int idx = i * 256 + tid;       // 0..1023
            const int r = idx >> 4;
            const int c = (idx & 15) * 8;
            *(uint4*)&Ks[r][c] = *(const uint4*)(kvbase + (size_t)r * NQKV + c);
            *(uint4*)&Vs[r][c] = *(const uint4*)(kvbase + (size_t)r * NQKV + INNER + c);
        }
        __syncthreads();

        if (kt * FA_BN > warp_max_row) continue;

        // ---- S = Q @ K^T -------------------------------------------------
        float sacc[8][4];
        #pragma unroll
        for (int ni = 0; ni < 8; ni++)
            #pragma unroll
            for (int e = 0; e < 4; e++) sacc[ni][e] = 0.f;

        #pragma unroll
        for (int ks = 0; ks < 8; ks++) {
            uint32_t kf[8][2];
            #pragma unroll
            for (int np = 0; np < 4; np++) {
                uint32_t td[4];
                ldm_x4(td, ksBase + (uint32_t)(
                    (np * 16 + (lane & 7) + ((lane >> 4) << 3)) * FA_SK
                    + ks * 16 + (lane & 8)) * 2);
                kf[2 * np][0]     = td[0];
                kf[2 * np][1]     = td[1];
                kf[2 * np + 1][0] = td[2];
                kf[2 * np + 1][1] = td[3];
            }
            #pragma unroll
            for (int ni = 0; ni < 8; ni++)
                mma_f16(sacc[ni], qf[ks], kf[ni]);
        }

        // ---- causal mask (diagonal tiles only) ---------------------------
        if (kt * FA_BN + FA_BN - 1 > warp_min_row) {
            #pragma unroll
            for (int ni = 0; ni < 8; ni++) {
                const int cg = kt * FA_BN + ni * 8 + 2 * (lane & 3);
                #pragma unroll
                for (int e = 0; e < 4; e++) {
                    const int col = cg + (e & 1);
                    const int row = qrow0 + (e >> 1) * 8;
                    if (col > row) sacc[ni][e] = -INFINITY;
                }
            }
        }

        // ---- online softmax (exp2 domain) --------------------------------
        float rmax0 = -INFINITY, rmax1 = -INFINITY;
        #pragma unroll
        for (int ni = 0; ni < 8; ni++) {
            rmax0 = fmaxf(rmax0, fmaxf(sacc[ni][0], sacc[ni][1]));
            rmax1 = fmaxf(rmax1, fmaxf(sacc[ni][2], sacc[ni][3]));
        }
        rmax0 = fmaxf(rmax0, __shfl_xor_sync(0xffffffffu, rmax0, 1));
        rmax0 = fmaxf(rmax0, __shfl_xor_sync(0xffffffffu, rmax0, 2));
        rmax1 = fmaxf(rmax1, __shfl_xor_sync(0xffffffffu, rmax1, 1));
        rmax1 = fmaxf(rmax1, __shfl_xor_sync(0xffffffffu, rmax1, 2));

        const float mn0 = fmaxf(m0, rmax0);
        const float mn1 = fmaxf(m1, rmax1);
        const float c0 = fex2(m0 - mn0);
        const float c1 = fex2(m1 - mn1);
        float ps0 = 0.f, ps1 = 0.f;
        #pragma unroll
        for (int ni = 0; ni < 8; ni++) {
            sacc[ni][0] = fex2(sacc[ni][0] - mn0);
            sacc[ni][1] = fex2(sacc[ni][1] - mn0);
            sacc[ni][2] = fex2(sacc[ni][2] - mn1);
            sacc[ni][3] = fex2(sacc[ni][3] - mn1);
            ps0 += sacc[ni][0] + sacc[ni][1];
            ps1 += sacc[ni][2] + sacc[ni][3];
        }
        ps0 += __shfl_xor_sync(0xffffffffu, ps0, 1);
        ps0 += __shfl_xor_sync(0xffffffffu, ps0, 2);
        ps1 += __shfl_xor_sync(0xffffffffu, ps1, 1);
        ps1 += __shfl_xor_sync(0xffffffffu, ps1, 2);
        l0 = l0 * c0 + ps0;
        l1 = l1 * c1 + ps1;
        m0 = mn0;
        m1 = mn1;
        #pragma unroll
        for (int nd = 0; nd < 16; nd++) {
            oacc[nd][0] *= c0;
            oacc[nd][1] *= c0;
            oacc[nd][2] *= c1;
            oacc[nd][3] *= c1;
        }

        // ---- O += P @ V  (C-frag == A-frag layout) -----------------------
        #pragma unroll
        for (int j = 0; j < 4; j++) {
            uint32_t a[4];
            a[0] = f2h2(sacc[2 * j][0],     sacc[2 * j][1]);
            a[1] = f2h2(sacc[2 * j][2],     sacc[2 * j][3]);
            a[2] = f2h2(sacc[2 * j + 1][0], sacc[2 * j + 1][1]);
            a[3] = f2h2(sacc[2 * j + 1][2], sacc[2 * j + 1][3]);
            #pragma unroll
            for (int np = 0; np < 8; np++) {
                uint32_t v[4];
                ldm_x4_t(v, vsBase + (uint32_t)(
                    (j * 16 + (lane & 15)) * FA_SK
                    + np * 16 + ((lane >> 4) << 3)) * 2);
                mma_f16(oacc[2 * np],     a, v);
                mma_f16(oacc[2 * np + 1], a, v + 2);
            }
        }
    }

    // epilogue (fp16 out)
    const float inv0 = 1.f / l0;
    const float inv1 = 1.f / l1;
    __half* ob = O + ((size_t)(b * N_SEQ + qt * FA_BM + warp * 16 + (lane >> 2))) * INNER
                   + h * DHEAD + 2 * (lane & 3);
    #pragma unroll
    for (int nd = 0; nd < 16; nd++) {
        *(uint32_t*)(ob + nd * 8) = f2h2(oacc[nd][0] * inv0, oacc[nd][1] * inv0);
        *(uint32_t*)(ob + (size_t)8 * INNER + nd * 8) =
            f2h2(oacc[nd][2] * inv1, oacc[nd][3] * inv1);
    }
}

// ----------------------------------------------------------------------------
// Launch
// ----------------------------------------------------------------------------
extern "C" void kernel_launch(void* const* d_in, const int* in_sizes, int n_in,
                              void* d_out, int out_size)
{
    const float* x   = (const float*)d_in[0];
    const float* re  = (const float*)d_in[1];
    const float* g   = (const float*)d_in[2];
    const float* Wq  = (const float*)d_in[3];
    const float* Wkv = (const float*)d_in[4];
    const float* Wo  = (const float*)d_in[5];
    float* out = (float*)d_out;

    __half *xn, *qkv, *o, *wqkv, *wo;
    cudaGetSymbolAddress((void**)&xn,   g_xn);
    cudaGetSymbolAddress((void**)&qkv,  g_qkv);
    cudaGetSymbolAddress((void**)&o,    g_o);
    cudaGetSymbolAddress((void**)&wqkv, g_wqkv);
    cudaGetSymbolAddress((void**)&wo,   g_wo);

    // 0) weight conversion fp32 -> fp16 (fused Wq|Wkv, plus Wo)
    cvtw_kernel<<<(DIM * INNER / 4 + 255) / 256, 256>>>(
        Wq, wqkv, INNER, NQKV, 0, DIM * INNER);
    cvtw_kernel<<<(DIM * 2 * INNER / 4 + 255) / 256, 256>>>(
        Wkv, wqkv, 2 * INNER, NQKV, INNER, DIM * 2 * INNER);
    cvtw_kernel<<<(INNER * DIM / 4 + 255) / 256, 256>>>(
        Wo, wo, DIM, DIM, 0, INNER * DIM);

    // 1) RMSNorm (fp16 out)
    rmsnorm_kernel<<<ROWS, 256>>>(x, g, xn);

    // 2) fused qkv projection (fp16 x fp16 -> fp16)
    dim3 gp(NQKV / 128, ROWS / 128);             // (48, 32)
    h16_gemm_kernel<__half><<<gp, 256>>>(ROWS, NQKV, DIM, xn, wqkv, qkv);

    // 3) RoPE on q and k (one launch, fp16, fused buffer)
    const size_t ropeN = 2 * (size_t)ROWS * HEADS * 64;
    const int ropeBlocks = (int)((ropeN + 255) / 256);
    rope2_kernel<<<ropeBlocks, 256>>>(qkv, re);

    // 4) causal attention (fp16, fused qkv)
    dim3 ga(N_SEQ / FA_BM, B * HEADS);
    attn_h16_kernel<<<ga, 256>>>(qkv, o);

    // 5) output projection (fp16 x fp16 -> fp32)
    dim3 go(DIM / 128, ROWS / 128);              // (16, 32)
    h16_gemm_kernel<float><<<go, 256>>>(ROWS, DIM, DIM, o, wo, out);
}

// round 12
// speedup vs baseline: 2.1939x; 1.0636x over previous
#include <cuda_runtime.h>
#include <cuda_fp16.h>
#include <math.h>
#include <stdint.h>

// ----------------------------------------------------------------------------
// Problem constants
// ----------------------------------------------------------------------------
#define B      2
#define N_SEQ  2048
#define DIM    2048
#define HEADS  16
#define DHEAD  128
#define INNER  (HEADS * DHEAD)       // 2048
#define ROWS   (B * N_SEQ)           // 4096
#define NQKV   (3 * INNER)           // 6144 fused projection width

// ----------------------------------------------------------------------------
// Scratch (device globals; no allocations allowed)
// ----------------------------------------------------------------------------
__device__ __half g_xn  [ROWS * DIM];
__device__ __half g_qkv [ROWS * NQKV];
__device__ __half g_o   [ROWS * INNER];
__device__ __half g_wqkv[DIM * NQKV];
__device__ __half g_wo  [INNER * DIM];
__device__ float  g_cos [N_SEQ * DHEAD];
__device__ float  g_sin [N_SEQ * DHEAD];

// ----------------------------------------------------------------------------
// helpers
// ----------------------------------------------------------------------------
__device__ __forceinline__ uint32_t f2h2(float lo, float hi) {
    uint32_t r;
    asm("cvt.rn.f16x2.f32 %0, %1, %2;" : "=r"(r) : "f"(hi), "f"(lo));
    return r;
}

__device__ __forceinline__ uint32_t hmul2(uint32_t a, uint32_t b) {
    uint32_t r;
    asm("mul.rn.f16x2 %0, %1, %2;" : "=r"(r) : "r"(a), "r"(b));
    return r;
}

__device__ __forceinline__ float fex2(float x) {
    float y;
    asm("ex2.approx.ftz.f32 %0, %1;" : "=f"(y) : "f"(x));
    return y;
}

__device__ __forceinline__ void mma_f16(float* c, const uint32_t* a, const uint32_t* b) {
    asm volatile(
        "mma.sync.aligned.m16n8k16.row.col.f32.f16.f16.f32 "
        "{%0,%1,%2,%3},{%4,%5,%6,%7},{%8,%9},{%0,%1,%2,%3};"
        : "+f"(c[0]), "+f"(c[1]), "+f"(c[2]), "+f"(c[3])
        : "r"(a[0]), "r"(a[1]), "r"(a[2]), "r"(a[3]), "r"(b[0]), "r"(b[1]));
}

__device__ __forceinline__ void ldm_x4(uint32_t* d, uint32_t addr) {
    asm volatile("ldmatrix.sync.aligned.m8n8.x4.shared.b16 {%0,%1,%2,%3}, [%4];"
                 : "=r"(d[0]), "=r"(d[1]), "=r"(d[2]), "=r"(d[3]) : "r"(addr));
}
__device__ __forceinline__ void ldm_x4_t(uint32_t* d, uint32_t addr) {
    asm volatile("ldmatrix.sync.aligned.m8n8.x4.trans.shared.b16 {%0,%1,%2,%3}, [%4];"
                 : "=r"(d[0]), "=r"(d[1]), "=r"(d[2]), "=r"(d[3]) : "r"(addr));
}

__device__ __forceinline__ uint32_t smem_u32(const void* p) {
    uint32_t a;
    asm("{ .reg .u64 t; cvta.to.shared.u64 t, %1; cvt.u32.u64 %0, t; }"
        : "=r"(a) : "l"(p));
    return a;
}

__device__ __forceinline__ void cpa16(uint32_t saddr, const void* g) {
    asm volatile("cp.async.cg.shared.global [%0], [%1], 16;" :: "r"(saddr), "l"(g));
}
#define CPA_COMMIT() asm volatile("cp.async.commit_group;" ::: "memory")
#define CPA_WAIT0()  asm volatile("cp.async.wait_group 0;"  ::: "memory")

// ----------------------------------------------------------------------------
// Weight fp32 -> fp16 conversion (with column remap into fused buffers)
// ----------------------------------------------------------------------------
__global__ __launch_bounds__(256) void cvtw_kernel(
    const float* __restrict__ src, __half* __restrict__ dst,
    int src_ncols, int dst_ncols, int col_off, int n)
{
    const int idx = (blockIdx.x * 256 + threadIdx.x) * 4;
    if (idx >= n) return;
    const int r = idx / src_ncols;
    const int c = idx - r * src_ncols;
    float4 v = *(const float4*)(src + idx);
    *(uint2*)(dst + (size_t)r * dst_ncols + col_off + c) =
        make_uint2(f2h2(v.x, v.y), f2h2(v.z, v.w));
}

// ----------------------------------------------------------------------------
// cos/sin table precompute (same cosf/sinf bits as before)
// ----------------------------------------------------------------------------
__global__ __launch_bounds__(256) void sincos_kernel(
    const float* __restrict__ re, float* __restrict__ ct, float* __restrict__ st)
{
    const int i = blockIdx.x * 256 + threadIdx.x;
    if (i < N_SEQ * DHEAD) {
        const float p = re[i];
        ct[i] = cosf(p);
        st[i] = sinf(p);
    }
}

// ----------------------------------------------------------------------------
// RMSNorm -> fp16 output (float4 path)
// ----------------------------------------------------------------------------
__global__ __launch_bounds__(256) void rmsnorm_kernel(
    const float* __restrict__ x, const float* __restrict__ g,
    __half* __restrict__ xn)
{
    const int row = blockIdx.x;
    const float* xr = x  + (size_t)row * DIM;
    __half*      xo = xn + (size_t)row * DIM;

    float ss = 0.f;
    #pragma unroll
    for (int i = threadIdx.x * 4; i < DIM; i += 1024) {
        float4 v = *(const float4*)(xr + i);
        ss += v.x * v.x + v.y * v.y + v.z * v.z + v.w * v.w;
    }
    __shared__ float red[8];
    #pragma unroll
    for (int o = 16; o > 0; o >>= 1) ss += __shfl_xor_sync(0xffffffffu, ss, o);
    if ((threadIdx.x & 31) == 0) red[threadIdx.x >> 5] = ss;
    __syncthreads();
    if (threadIdx.x < 8) {
        float v = red[threadIdx.x];
        #pragma unroll
        for (int o = 4; o > 0; o >>= 1) v += __shfl_xor_sync(0x000000ffu, v, o);
        if (threadIdx.x == 0) red[0] = v;
    }
    __syncthreads();
    const float rms = sqrtf(red[0] * (1.f / (float)DIM));
    const float inv = 1.f / fmaxf(rms, 1e-8f);
    #pragma unroll
    for (int i = threadIdx.x * 4; i < DIM; i += 1024) {
        float4 v = *(const float4*)(xr + i);
        float4 gg = *(const float4*)(g + i);
        *(uint2*)(xo + i) = make_uint2(
            f2h2(v.x * inv * gg.x, v.y * inv * gg.y),
            f2h2(v.z * inv * gg.z, v.w * inv * gg.w));
    }
}

// ----------------------------------------------------------------------------
// FP16 tensor-core GEMM (m16n8k16), cp.async double-buffered, ldmatrix.
// ----------------------------------------------------------------------------
#define G_BK 32
#define G_SA 40
#define G_SB 136
#define G_ABUF (128 * G_SA * 2)     // bytes per A stage
#define G_BBUF (G_BK * G_SB * 2)    // bytes per B stage

template <typename OutT>
__global__ __launch_bounds__(256, 2) void h16_gemm_kernel(
    int M, int N, int K,
    const __half* __restrict__ A, const __half* __restrict__ Bm,
    OutT* __restrict__ C)
{
    __shared__ __half As[2][128][G_SA];
    __shared__ __half Bs[2][G_BK][G_SB];

    const int tid  = threadIdx.x;
    const int lane = tid & 31;
    const int warp = tid >> 5;
    const int mbase = (warp >> 1) * 32;
    const int nbase = (warp & 1) * 64;

    const int aRow = tid >> 1;
    const int aCol = (tid & 1) * 16;
    const int bRow = tid >> 4;
    const int bCol = (tid & 15) * 8;

    const __half* Ap = A  + (size_t)blockIdx.y * 128 * K;
    const __half* Bp = Bm + (size_t)blockIdx.x * 128;

    const uint32_t asBase = smem_u32(As);
    const uint32_t bsBase = smem_u32(Bs);
    const uint32_t aDst = asBase + (uint32_t)(aRow * G_SA + aCol) * 2;
    const uint32_t bDst0 = bsBase + (uint32_t)(bRow * G_SB + bCol) * 2;
    const uint32_t bDst1 = bsBase + (uint32_t)((bRow + 16) * G_SB + bCol) * 2;
    const int lrow = lane & 15;
    const int lcb  = (lane >> 4) << 3;

    // issue tile 0
    {
        const __half* Ar = Ap + (size_t)aRow * K + aCol;
        cpa16(aDst,      Ar);
        cpa16(aDst + 16, Ar + 8);
        cpa16(bDst0, Bp + (size_t)bRow        * N + bCol);
        cpa16(bDst1, Bp + (size_t)(bRow + 16) * N + bCol);
        CPA_COMMIT();
    }
    CPA_WAIT0();
    __syncthreads();

    float acc[2][8][4];
    #pragma unroll
    for (int mi = 0; mi < 2; mi++)
        #pragma unroll
        for (int ni = 0; ni < 8; ni++)
            #pragma unroll
            for (int e = 0; e < 4; e++) acc[mi][ni][e] = 0.f;

    const int nT = K / G_BK;
    for (int t = 0; t < nT; t++) {
        const int cur = t & 1;

        if (t + 1 < nT) {
            const uint32_t boff = (uint32_t)((t + 1) & 1);
            const __half* Ar = Ap + (size_t)aRow * K + (t + 1) * G_BK + aCol;
            cpa16(aDst + boff * G_ABUF,      Ar);
            cpa16(aDst + boff * G_ABUF + 16, Ar + 8);
            const __half* Br = Bp + (size_t)((t + 1) * G_BK) * N;
            cpa16(bDst0 + boff * G_BBUF, Br + (size_t)bRow        * N + bCol);
            cpa16(bDst1 + boff * G_BBUF, Br + (size_t)(bRow + 16) * N + bCol);
            CPA_COMMIT();
        }

        const uint32_t asB = asBase + (uint32_t)cur * G_ABUF;
        const uint32_t bsB = bsBase + (uint32_t)cur * G_BBUF;
        #pragma unroll
        for (int ks = 0; ks < G_BK; ks += 16) {
            uint32_t af[2][4];
            ldm_x4(af[0], asB + (uint32_t)((mbase      + lrow) * G_SA + ks + lcb) * 2);
            ldm_x4(af[1], asB + (uint32_t)((mbase + 16 + lrow) * G_SA + ks + lcb) * 2);
            uint32_t bf[8][2];
            #pragma unroll
            for (int nb = 0; nb < 4; nb++) {
                uint32_t td[4];
                ldm_x4_t(td, bsB + (uint32_t)((ks + lrow) * G_SB + nbase + nb * 16 + lcb) * 2);
                bf[2 * nb][0]     = td[0];
                bf[2 * nb][1]     = td[1];
                bf[2 * nb + 1][0] = td[2];
                bf[2 * nb + 1][1] = td[3];
            }
            #pragma unroll
            for (int mi = 0; mi < 2; mi++)
                #pragma unroll
                for (int ni = 0; ni < 8; ni++)
                    mma_f16(acc[mi][ni], af[mi], bf[ni]);
        }

        if (t + 1 < nT) CPA_WAIT0();
        __syncthreads();
    }

    OutT* Cp = C + (size_t)(blockIdx.y * 128 + mbase) * N + blockIdx.x * 128 + nbase;
    #pragma unroll
    for (int mi = 0; mi < 2; mi++) {
        const int r = mi * 16 + (lane >> 2);
        #pragma unroll
        for (int ni = 0; ni < 8; ni++) {
            const int c = ni * 8 + (lane & 3) * 2;
            if constexpr (sizeof(OutT) == 2) {
                *(uint32_t*)(Cp + (size_t)r       * N + c) = f2h2(acc[mi][ni][0], acc[mi][ni][1]);
                *(uint32_t*)(Cp + (size_t)(r + 8) * N + c) = f2h2(acc[mi][ni][2], acc[mi][ni][3]);
            } else {
                *(float2*)(Cp + (size_t)r       * N + c) = make_float2(acc[mi][ni][0], acc[mi][ni][1]);
                *(float2*)(Cp + (size_t)(r + 8) * N + c) = make_float2(acc[mi][ni][2], acc[mi][ni][3]);
            }
        }
    }
}

// ----------------------------------------------------------------------------
// RoPE (in place, fused qkv) using precomputed cos/sin tables.
// ----------------------------------------------------------------------------
__global__ __launch_bounds__(256) void rope2_kernel(
    __half* __restrict__ qkv, const float* __restrict__ ct, const float* __restrict__ st)
{
    const size_t half_n = (size_t)ROWS * HEADS * 64;
    size_t idx = (size_t)blockIdx.x * blockDim.x + threadIdx.x;
    int coff;
    if (idx >= half_n) {
        if (idx >= 2 * half_n) return;
        idx -= half_n;
        coff = INNER;
    } else {
        coff = 0;
    }
    const int d = (int)(idx & 63);
    const int h = (int)((idx >> 6) & (HEADS - 1));
    const int r = (int)(idx >> 10);
    const int n = r & (N_SEQ - 1);

    __half* base = qkv + (size_t)r * NQKV + coff + h * DHEAD;
    const float c1 = ct[n * DHEAD + d];
    const float s1 = st[n * DHEAD + d];
    const float c2 = ct[n * DHEAD + d + 64];
    const float s2 = st[n * DHEAD + d + 64];
    const float t1 = __half2float(base[d]);
    const float t2 = __half2float(base[d + 64]);
    base[d]      = __float2half(t1 * c1 - t2 * s1);
    base[d + 64] = __float2half(t2 * c2 + t1 * s2);
}

// ----------------------------------------------------------------------------
// Causal flash attention, fp16 m16n8k16, fused-qkv input. (unchanged)
// ----------------------------------------------------------------------------
#define FA_BM 128
#define FA_BN 64
#define FA_SK 136

__global__ __launch_bounds__(256, 1) void attn_h16_kernel(
    const __half* __restrict__ QKV, __half* __restrict__ O)
{
    __shared__ __half Ks[FA_BN][FA_SK];
    __shared__ __half Vs[FA_BN][FA_SK];

    const int bh = blockIdx.y;
    const int b  = bh >> 4;
    const int h  = bh & 15;
    const int qt = gridDim.x - 1 - blockIdx.x;

    const int tid  = threadIdx.x;
    const int lane = tid & 31;
    const int warp = tid >> 5;

    const uint32_t ksBase = smem_u32(Ks);
    const uint32_t vsBase = smem_u32(Vs);

    const float qsf = 0.088388347648318447f * 1.4426950408889634f;
    const uint32_t qs2 = f2h2(qsf, qsf);
    uint32_t qf[8][4];
    {
        const __half* qb = QKV + ((size_t)(b * N_SEQ + qt * FA_BM + warp * 16 + (lane >> 2))) * NQKV
                               + h * DHEAD;
        #pragma unroll
        for (int ks = 0; ks < 8; ks++) {
            const int k0 = ks * 16 + 2 * (lane & 3);
            qf[ks][0] = hmul2(*(const uint32_t*)(qb + k0), qs2);
            qf[ks][1] = hmul2(*(const uint32_t*)(qb + 8 * NQKV + k0), qs2);
            qf[ks][2] = hmul2(*(const uint32_t*)(qb + k0 + 8), qs2);
            qf[ks][3] = hmul2(*(const uint32_t*)(qb + 8 * NQKV + k0 + 8), qs2);
        }
    }

    float oacc[16][4];
    #pragma unroll
    for (int nd = 0; nd < 16; nd++)
        #pragma unroll
        for (int e = 0; e < 4; e++) oacc[nd][e] = 0.f;

    float m0 = -INFINITY, m1 = -INFINITY, l0 = 0.f, l1 = 0.f;
    const int qrow0 = qt * FA_BM + warp * 16 + (lane >> 2);
    const int warp_min_row = qt * FA_BM + warp * 16;
    const int warp_max_row = warp_min_row + 15;

    const int ntiles = 2 * qt + 2;
    for (int kt = 0; kt < ntiles; kt++) {
        __syncthreads();
        const __half* kvbase = QKV + ((size_t)(b * N_SEQ + kt * FA_BN)) * NQKV
                                   + INNER + h * DHEAD;
        #pragma unroll
        for (int i = 0; i < 4; i++) {
            const int idx = i * 256 + tid;
            const int r = idx >> 4;
            const int c = (idx & 15) * 8;
            *(uint4*)&Ks[r][c] = *(const uint4*)(kvbase + (size_t)r * NQKV + c);
            *(uint4*)&Vs[r][c] = *(const uint4*)(kvbase + (size_t)r * NQKV + INNER + c);
        }
        __syncthreads();

        if (kt * FA_BN > warp_max_row) continue;

        float sacc[8][4];
        #pragma unroll
        for (int ni = 0; ni < 8; ni++)
            #pragma unroll
            for (int e = 0; e < 4; e++) sacc[ni][e] = 0.f;

        #pragma unroll
        for (int ks = 0; ks < 8; ks++) {
            uint32_t kf[8][2];
            #pragma unroll
            for (int np = 0; np < 4; np++) {
                uint32_t td[4];
                ldm_x4(td, ksBase + (uint32_t)(
                    (np * 16 + (lane & 7) + ((lane >> 4) << 3)) * FA_SK
                    + ks * 16 + (lane & 8)) * 2);
                kf[2 * np][0]     = td[0];
                kf[2 * np][1]     = td[1];
                kf[2 * np + 1][0] = td[2];
                kf[2 * np + 1][1] = td[3];
            }
            #pragma unroll
            for (int ni = 0; ni < 8; ni++)
                mma_f16(sacc[ni], qf[ks], kf[ni]);
        }

        if (kt * FA_BN + FA_BN - 1 > warp_min_row) {
            #pragma unroll
            for (int ni = 0; ni < 8; ni++) {
                const int cg = kt * FA_BN + ni * 8 + 2 * (lane & 3);
                #pragma unroll
                for (int e = 0; e < 4; e++) {
                    const int col = cg + (e & 1);
                    const int row = qrow0 + (e >> 1) * 8;
                    if (col > row) sacc[ni][e] = -INFINITY;
                }
            }
        }

        float rmax0 = -INFINITY, rmax1 = -INFINITY;
        #pragma unroll
        for (int ni = 0; ni < 8; ni++) {
            rmax0 = fmaxf(rmax0, fmaxf(sacc[ni][0], sacc[ni][1]));
            rmax1 = fmaxf(rmax1, fmaxf(sacc[ni][2], sacc[ni][3]));
        }
        rmax0 = fmaxf(rmax0, __shfl_xor_sync(0xffffffffu, rmax0, 1));
        rmax0 = fmaxf(rmax0, __shfl_xor_sync(0xffffffffu, rmax0, 2));
        rmax1 = fmaxf(rmax1, __shfl_xor_sync(0xffffffffu, rmax1, 1));
        rmax1 = fmaxf(rmax1, __shfl_xor_sync(0xffffffffu, rmax1, 2));

        const float mn0 = fmaxf(m0, rmax0);
        const float mn1 = fmaxf(m1, rmax1);
        const float c0 = fex2(m0 - mn0);
        const float c1 = fex2(m1 - mn1);
        float ps0 = 0.f, ps1 = 0.f;
        #pragma unroll
        for (int ni = 0; ni < 8; ni++) {
            sacc[ni][0] = fex2(sacc[ni][0] - mn0);
            sacc[ni][1] = fex2(sacc[ni][1] - mn0);
            sacc[ni][2] = fex2(sacc[ni][2] - mn1);
            sacc[ni][3] = fex2(sacc[ni][3] - mn1);
            ps0 += sacc[ni][0] + sacc[ni][1];
            ps1 += sacc[ni][2] + sacc[ni][3];
        }
        ps0 += __shfl_xor_sync(0xffffffffu, ps0, 1);
        ps0 += __shfl_xor_sync(0xffffffffu, ps0, 2);
        ps1 += __shfl_xor_sync(0xffffffffu, ps1, 1);
        ps1 += __shfl_xor_sync(0xffffffffu, ps1, 2);
        l0 = l0 * c0 + ps0;
        l1 = l1 * c1 + ps1;
        m0 = mn0;
        m1 = mn1;
        #pragma unroll
        for (int nd = 0; nd < 16; nd++) {
            oacc[nd][0] *= c0;
            oacc[nd][1] *= c0;
            oacc[nd][2] *= c1;
            oacc[nd][3] *= c1;
        }

        #pragma unroll
        for (int j = 0; j < 4; j++) {
            uint32_t a[4];
            a[0] = f2h2(sacc[2 * j][0],     sacc[2 * j][1]);
            a[1] = f2h2(sacc[2 * j][2],     sacc[2 * j][3]);
            a[2] = f2h2(sacc[2 * j + 1][0], sacc[2 * j + 1][1]);
            a[3] = f2h2(sacc[2 * j + 1][2], sacc[2 * j + 1][3]);
            #pragma unroll
            for (int np = 0; np < 8; np++) {
                uint32_t v[4];
                ldm_x4_t(v, vsBase + (uint32_t)(
                    (j * 16 + (lane & 15)) * FA_SK
                    + np * 16 + ((lane >> 4) << 3)) * 2);
                mma_f16(oacc[2 * np],     a, v);
                mma_f16(oacc[2 * np + 1], a, v + 2);
            }
        }
    }

    const float inv0 = 1.f / l0;
    const float inv1 = 1.f / l1;
    __half* ob = O + ((size_t)(b * N_SEQ + qt * FA_BM + warp * 16 + (lane >> 2))) * INNER
                   + h * DHEAD + 2 * (lane & 3);
    #pragma unroll
    for (int nd = 0; nd < 16; nd++) {
        *(uint32_t*)(ob + nd * 8) = f2h2(oacc[nd][0] * inv0, oacc[nd][1] * inv0);
        *(uint32_t*)(ob + (size_t)8 * INNER + nd * 8) =
            f2h2(oacc[nd][2] * inv1, oacc[nd][3] * inv1);
    }
}

// ----------------------------------------------------------------------------
// Launch
// ----------------------------------------------------------------------------
extern "C" void kernel_launch(void* const* d_in, const int* in_sizes, int n_in,
                              void* d_out, int out_size)
{
    const float* x   = (const float*)d_in[0];
    const float* re  = (const float*)d_in[1];
    const float* g   = (const float*)d_in[2];
    const float* Wq  = (const float*)d_in[3];
    const float* Wkv = (const float*)d_in[4];
    const float* Wo  = (const float*)d_in[5];
    float* out = (float*)d_out;

    __half *xn, *qkv, *o, *wqkv, *wo;
    float *ct, *st;
    cudaGetSymbolAddress((void**)&xn,   g_xn);
    cudaGetSymbolAddress((void**)&qkv,  g_qkv);
    cudaGetSymbolAddress((void**)&o,    g_o);
    cudaGetSymbolAddress((void**)&wqkv, g_wqkv);
    cudaGetSymbolAddress((void**)&wo,   g_wo);
    cudaGetSymbolAddress((void**)&ct,   g_cos);
    cudaGetSymbolAddress((void**)&st,   g_sin);

    // 0) weight conversion + cos/sin tables
    cvtw_kernel<<<(DIM * INNER / 4 + 255) / 256, 256>>>(
        Wq, wqkv, INNER, NQKV, 0, DIM * INNER);
    cvtw_kernel<<<(DIM * 2 * INNER / 4 + 255) / 256, 256>>>(
        Wkv, wqkv, 2 * INNER, NQKV, INNER, DIM * 2 * INNER);
    cvtw_kernel<<<(INNER * DIM / 4 + 255) / 256, 256>>>(
        Wo, wo, DIM, DIM, 0, INNER * DIM);
    sincos_kernel<<<(N_SEQ * DHEAD + 255) / 256, 256>>>(re, ct, st);

    // 1) RMSNorm (fp16 out)
    rmsnorm_kernel<<<ROWS, 256>>>(x, g, xn);

    // 2) fused qkv projection
    dim3 gp(NQKV / 128, ROWS / 128);
    h16_gemm_kernel<__half><<<gp, 256>>>(ROWS, NQKV, DIM, xn, wqkv, qkv);

    // 3) RoPE (table-based)
    const size_t ropeN = 2 * (size_t)ROWS * HEADS * 64;
    const int ropeBlocks = (int)((ropeN + 255) / 256);
    rope2_kernel<<<ropeBlocks, 256>>>(qkv, ct, st);

    // 4) causal attention
    dim3 ga(N_SEQ / FA_BM, B * HEADS);
    attn_h16_kernel<<<ga, 256>>>(qkv, o);

    // 5) output projection
    dim3 go(DIM / 128, ROWS / 128);
    h16_gemm_kernel<float><<<go, 256>>>(ROWS, DIM, DIM, o, wo, out);
}